// round 15
// baseline (speedup 1.0000x reference)
#include <cuda_runtime.h>
#include <cuda_bf16.h>

typedef unsigned long long ull;
constexpr int BATCH = 256;

// ---------------- scratch (device globals) ----------------
__device__ __align__(16) float g_out1[BATCH * 64 * 256];
__device__ __align__(16) float g_fc1p[16 * BATCH * 1024];
__device__ __align__(16) float g_r1a[1728];
__device__ __align__(16) float g_r1b[1728];
__device__ __align__(16) __nv_bfloat16 g_o1h[BATCH * 16384];  // out1 hi [t][c]
__device__ __align__(16) __nv_bfloat16 g_o1l[BATCH * 16384];
__device__ __align__(16) __nv_bfloat16 g_w2ah[9 * 32 * 64];   // conv W [tap][oc][c]
__device__ __align__(16) __nv_bfloat16 g_w2al[9 * 32 * 64];
__device__ __align__(16) __nv_bfloat16 g_w2bh[9 * 32 * 64];   // knn W [tap][oc][c]
__device__ __align__(16) __nv_bfloat16 g_w2bl[9 * 32 * 64];
__device__ __align__(16) __nv_bfloat16 g_c2h[BATCH * 16384];  // cat2 hi [t][c]
__device__ __align__(16) __nv_bfloat16 g_c2l[BATCH * 16384];
__device__ __align__(16) __nv_bfloat16 g_wph[8192];           // w2p hi [oc][c]
__device__ __align__(16) __nv_bfloat16 g_wpl[8192];
__device__ __align__(16) __nv_bfloat16 g_ahi[BATCH * 32768];
__device__ __align__(16) __nv_bfloat16 g_alo[BATCH * 32768];

// ---------------- f32x2 helpers ----------------
__device__ __forceinline__ ull pack2(float lo, float hi) {
    ull r;
    asm("mov.b64 %0, {%1, %2};" : "=l"(r) : "r"(__float_as_uint(lo)), "r"(__float_as_uint(hi)));
    return r;
}
__device__ __forceinline__ ull packd(float s) { return pack2(s, s); }
__device__ __forceinline__ void fma2(ull& d, ull a, ull b) {
    asm("fma.rn.f32x2 %0, %1, %2, %3;" : "=l"(d) : "l"(a), "l"(b), "l"(d));
}
__device__ __forceinline__ float2 unpk(ull v) {
    unsigned lo, hi;
    asm("mov.b64 {%0, %1}, %2;" : "=r"(lo), "=r"(hi) : "l"(v));
    float2 f; f.x = __uint_as_float(lo); f.y = __uint_as_float(hi);
    return f;
}

// ---------------- mma.sync helpers ----------------
__device__ __forceinline__ unsigned smem_u32(const void* p) {
    unsigned a;
    asm("{ .reg .u64 t; cvta.to.shared.u64 t, %1; cvt.u32.u64 %0, t; }" : "=r"(a) : "l"(p));
    return a;
}
__device__ __forceinline__ void ldsm4(unsigned& r0, unsigned& r1, unsigned& r2, unsigned& r3,
                                      unsigned addr) {
    asm volatile("ldmatrix.sync.aligned.m8n8.x4.shared.b16 {%0,%1,%2,%3}, [%4];"
                 : "=r"(r0), "=r"(r1), "=r"(r2), "=r"(r3) : "r"(addr));
}
__device__ __forceinline__ void mma16816(float* c, const unsigned* a, const unsigned* b) {
    asm volatile(
        "mma.sync.aligned.m16n8k16.row.col.f32.bf16.bf16.f32 "
        "{%0,%1,%2,%3},{%4,%5,%6,%7},{%8,%9},{%0,%1,%2,%3};"
        : "+f"(c[0]), "+f"(c[1]), "+f"(c[2]), "+f"(c[3])
        : "r"(a[0]), "r"(a[1]), "r"(a[2]), "r"(a[3]), "r"(b[0]), "r"(b[1]));
}
__device__ __forceinline__ void cpa16(unsigned dst, const void* src) {
    asm volatile("cp.async.cg.shared.global [%0], [%1], 16;" :: "r"(dst), "l"(src));
}
__device__ __forceinline__ void cpa_commit() { asm volatile("cp.async.commit_group;"); }
__device__ __forceinline__ void cpa_wait0() {
    asm volatile("cp.async.wait_group 0;" ::: "memory");
}
__device__ __forceinline__ void cpa_wait1() {
    asm volatile("cp.async.wait_group 1;" ::: "memory");
}
__device__ __forceinline__ void sts128(unsigned addr, uint4 v) {
    asm volatile("st.shared.v4.b32 [%0], {%1,%2,%3,%4};"
                 :: "r"(addr), "r"(v.x), "r"(v.y), "r"(v.z), "r"(v.w));
}
__device__ __forceinline__ unsigned pkbf(float a, float b) {
    __nv_bfloat16 ha = __float2bfloat16(a), hb = __float2bfloat16(b);
    return ((unsigned)__bfloat16_as_ushort(hb) << 16) | __bfloat16_as_ushort(ha);
}
__device__ __forceinline__ void wsplit_store(unsigned hi_base, int row, int c,
                                             float4 a, float4 b) {
    unsigned sw = (unsigned)(row * 64 + ((c ^ ((row >> 1) & 3)) << 4));
    uint4 hi, lo;
    hi.x = pkbf(a.x, a.y); hi.y = pkbf(a.z, a.w);
    hi.z = pkbf(b.x, b.y); hi.w = pkbf(b.z, b.w);
    __nv_bfloat16 t0 = __float2bfloat16(a.x), t1 = __float2bfloat16(a.y);
    __nv_bfloat16 t2 = __float2bfloat16(a.z), t3 = __float2bfloat16(a.w);
    __nv_bfloat16 t4 = __float2bfloat16(b.x), t5 = __float2bfloat16(b.y);
    __nv_bfloat16 t6 = __float2bfloat16(b.z), t7 = __float2bfloat16(b.w);
    lo.x = pkbf(a.x - __bfloat162float(t0), a.y - __bfloat162float(t1));
    lo.y = pkbf(a.z - __bfloat162float(t2), a.w - __bfloat162float(t3));
    lo.z = pkbf(b.x - __bfloat162float(t4), b.y - __bfloat162float(t5));
    lo.w = pkbf(b.z - __bfloat162float(t6), b.w - __bfloat162float(t7));
    sts128(hi_base + sw, hi);
    sts128(hi_base + 8192 + sw, lo);
}
__device__ __forceinline__ void c2_store(long base, float r0, float r1) {
    __nv_bfloat16 h0 = __float2bfloat16(r0), h1 = __float2bfloat16(r1);
    *(unsigned*)&g_c2h[base] = pkbf(r0, r1);
    *(unsigned*)&g_c2l[base] = pkbf(r0 - __bfloat162float(h0), r1 - __bfloat162float(h1));
}

// ---------------- weight repack ----------------
__global__ __launch_bounds__(256) void k_repack(const float* __restrict__ w1a,
                                                const float* __restrict__ w1b,
                                                const float* __restrict__ w2a,
                                                const float* __restrict__ w2b,
                                                const float* __restrict__ w2p) {
    int i = blockIdx.x * 256 + threadIdx.x;
    if (i < 1728) {
        int oc = i / 108, rest = i % 108;
        g_r1a[rest * 16 + oc] = w1a[i];
        g_r1b[rest * 16 + oc] = w1b[i];
    }
    if (i < 8192) {
        float v = w2p[i];
        __nv_bfloat16 h = __float2bfloat16(v);
        g_wph[i] = h;
        g_wpl[i] = __float2bfloat16(v - __bfloat162float(h));
    }
    if (i < 18432) {
        int oc = i / 576, rest = i % 576;
        int c = rest / 9, k = rest % 9;
        float va = w2a[i];
        __nv_bfloat16 ha = __float2bfloat16(va);
        g_w2ah[(k * 32 + oc) * 64 + c] = ha;
        g_w2al[(k * 32 + oc) * 64 + c] = __float2bfloat16(va - __bfloat162float(ha));
        float vb = w2b[i];
        __nv_bfloat16 hb = __float2bfloat16(vb);
        g_w2bh[(k * 32 + oc) * 64 + c] = hb;
        g_w2bl[(k * 32 + oc) * 64 + c] = __float2bfloat16(vb - __bfloat162float(hb));
    }
}

// ======================= Layer 1 FUSED, pixel-split x2 ==========================
__global__ __launch_bounds__(128) void k_l1(const float* __restrict__ x,
                                            const int* __restrict__ idx,
                                            const float* __restrict__ b1a,
                                            const float* __restrict__ b1b,
                                            const float* __restrict__ wp,
                                            const float* __restrict__ bp) {
    __shared__ __align__(16) float xs[12 * 256];
    __shared__ __align__(16) float ss[12 * 64];
    __shared__ float sn[64];
    __shared__ __align__(16) float wsa[1728];
    __shared__ __align__(16) float wsb[1728];
    __shared__ __align__(16) float wsp[64 * 32];
    int b = blockIdx.x, tid = threadIdx.x;
    int p = blockIdx.y * 128 + tid;

    for (int i = tid; i < 12 * 256; i += 128) {
        int cu = i >> 8, t = i & 255;
        int h = t >> 4, w = t & 15;
        int c = cu >> 2, ii = (cu >> 1) & 1, jj = cu & 1;
        xs[i] = x[((b * 3 + c) * 32 + (2 * h + ii)) * 32 + 2 * w + jj];
    }
    for (int i = tid; i < 1728; i += 128) { wsa[i] = g_r1a[i]; wsb[i] = g_r1b[i]; }
    for (int i = tid; i < 64 * 32; i += 128) wsp[i] = wp[i];
    __syncthreads();
    for (int i = tid; i < 12 * 64; i += 128)
        ss[i] = xs[(i >> 6) * 256 + idx[i & 63]];
    __syncthreads();
    if (tid < 64) {
        float s = 0.f;
#pragma unroll
        for (int c = 0; c < 12; c++) { float v = ss[c * 64 + tid]; s += v * v; }
        sn[tid] = s;
    }
    __syncthreads();

    int h = p >> 4, w = p & 15;

    ull acv[8];
#pragma unroll
    for (int o = 0; o < 8; o++) acv[o] = pack2(b1a[2 * o], b1a[2 * o + 1]);
    for (int c = 0; c < 12; c++) {
        float pp[9];
#pragma unroll
        for (int dy = 0; dy < 3; dy++)
#pragma unroll
            for (int dx = 0; dx < 3; dx++) {
                int y = h + dy - 1, xq = w + dx - 1;
                pp[dy * 3 + dx] = (y >= 0 && y < 16 && xq >= 0 && xq < 16)
                                      ? xs[c * 256 + y * 16 + xq] : 0.f;
            }
#pragma unroll
        for (int tap = 0; tap < 9; tap++) {
            ull s2 = packd(pp[tap]);
            const longlong2* wv = (const longlong2*)&wsa[(c * 9 + tap) * 16];
#pragma unroll
            for (int q = 0; q < 4; q++) {
                longlong2 w4 = wv[q];
                fma2(acv[q * 2 + 0], s2, (ull)w4.x);
                fma2(acv[q * 2 + 1], s2, (ull)w4.y);
            }
        }
    }

    float xr[12]; float xn = 0.f;
#pragma unroll
    for (int c = 0; c < 12; c++) { float v = xs[c * 256 + p]; xr[c] = v; xn += v * v; }

    float bd[9]; int bi[9];
#pragma unroll
    for (int k = 0; k < 9; k++) { bd[k] = 3.0e38f; bi[k] = 0; }
    for (int n = 0; n < 64; n++) {
        float dot = 0.f;
#pragma unroll
        for (int c = 0; c < 12; c++) dot += xr[c] * ss[c * 64 + n];
        float d = xn + sn[n] - 2.f * dot;
        if (d < bd[8]) {
            bool placed = false;
#pragma unroll
            for (int j = 8; j > 0; --j) {
                if (!placed) {
                    if (d < bd[j - 1]) { bd[j] = bd[j - 1]; bi[j] = bi[j - 1]; }
                    else { bd[j] = d; bi[j] = n; placed = true; }
                }
            }
            if (!placed) { bd[0] = d; bi[0] = n; }
        }
    }

    ull akn[8];
#pragma unroll
    for (int o = 0; o < 8; o++) akn[o] = pack2(b1b[2 * o], b1b[2 * o + 1]);
#pragma unroll
    for (int c = 0; c < 12; c++) {
#pragma unroll
        for (int k = 0; k < 9; k++) {
            ull s2 = packd(ss[c * 64 + bi[k]]);
            const longlong2* wv = (const longlong2*)&wsb[(c * 9 + k) * 16];
#pragma unroll
            for (int q = 0; q < 4; q++) {
                longlong2 w4 = wv[q];
                fma2(akn[q * 2 + 0], s2, (ull)w4.x);
                fma2(akn[q * 2 + 1], s2, (ull)w4.y);
            }
        }
    }

    ull xv[16];
#pragma unroll
    for (int o = 0; o < 8; o++) {
        float2 v = unpk(acv[o]);
        xv[o] = pack2(fmaxf(v.x, 0.f), fmaxf(v.y, 0.f));
        float2 u = unpk(akn[o]);
        xv[8 + o] = pack2(fmaxf(u.x, 0.f), fmaxf(u.y, 0.f));
    }
    float vb[8];
    for (int oc = 0; oc < 64; oc++) {
        ull a2 = 0ull;
        const longlong2* wv = (const longlong2*)&wsp[oc * 32];
#pragma unroll
        for (int q = 0; q < 8; q++) {
            longlong2 w4 = wv[q];
            fma2(a2, xv[q * 2 + 0], (ull)w4.x);
            fma2(a2, xv[q * 2 + 1], (ull)w4.y);
        }
        float2 v = unpk(a2);
        float val = v.x + v.y + bp[oc];
        g_out1[(b * 64 + oc) * 256 + p] = val;
        vb[oc & 7] = val;
        if ((oc & 7) == 7) {
            uint4 hi, lo;
            hi.x = pkbf(vb[0], vb[1]); hi.y = pkbf(vb[2], vb[3]);
            hi.z = pkbf(vb[4], vb[5]); hi.w = pkbf(vb[6], vb[7]);
            float l[8];
#pragma unroll
            for (int j = 0; j < 8; j++)
                l[j] = vb[j] - __bfloat162float(__float2bfloat16(vb[j]));
            lo.x = pkbf(l[0], l[1]); lo.y = pkbf(l[2], l[3]);
            lo.z = pkbf(l[4], l[5]); lo.w = pkbf(l[6], l[7]);
            long base = (long)b * 16384 + p * 64 + (oc - 7);
            *(uint4*)&g_o1h[base] = hi;
            *(uint4*)&g_o1l[base] = lo;
        }
    }
}

// ========== Layer 2 conv 3x3: implicit-GEMM mma, weights from global ============
// smem: Xh 33024 | Xl 33024 = 66048 -> 2 blocks/SM.
__global__ __launch_bounds__(256, 2) void k_l2c(const float* __restrict__ ba) {
    extern __shared__ __align__(16) char smem[];
    unsigned sb = smem_u32(smem);
    const unsigned XH = 0, XL = 33024;
    int b = blockIdx.x, tid = threadIdx.x, lane = tid & 31, warp = tid >> 5;

    if (tid < 16) {
        uint4 z = make_uint4(0, 0, 0, 0);
        unsigned pl = (tid >> 3) ? XL : XH;
        sts128(sb + pl + 256 * 128 + ((tid & 7) << 4), z);
    }
#pragma unroll
    for (int j = 0; j < 8; j++) {
        int q = tid + j * 256;
        int row = q >> 3, ch = q & 7;
        unsigned sw = (unsigned)(row * 128 + ((ch ^ (row & 7)) << 4));
        cpa16(sb + XH + sw, g_o1h + (long)b * 16384 + row * 64 + ch * 8);
        cpa16(sb + XL + sw, g_o1l + (long)b * 16384 + row * 64 + ch * 8);
    }
    cpa_commit();
    cpa_wait0();
    __syncthreads();

    int n_base = warp * 32;
    int ri = lane & 7, mat = lane >> 3;
    int arow = lane >> 2, acol = (lane & 3) * 2;

    float acc[2][4][4];
#pragma unroll
    for (int i = 0; i < 2; i++)
#pragma unroll
        for (int j = 0; j < 4; j++)
#pragma unroll
            for (int q = 0; q < 4; q++) acc[i][j][q] = 0.f;

#pragma unroll
    for (int tap = 0; tap < 9; tap++) {
        int dy = tap / 3, dx = tap % 3;
        int rin[2];
#pragma unroll
        for (int ng = 0; ng < 2; ng++) {
            int t = n_base + ng * 16 + ri + ((mat >> 1) << 3);
            int h = (t >> 4) + dy - 1, w = (t & 15) + dx - 1;
            rin[ng] = ((unsigned)h < 16u && (unsigned)w < 16u) ? h * 16 + w : 256;
        }
#pragma unroll
        for (int k16 = 0; k16 < 4; k16++) {
            unsigned bh[4][2], bl[4][2];
            int chb = k16 * 2 + (mat & 1);
#pragma unroll
            for (int ng = 0; ng < 2; ng++) {
                int r = rin[ng];
                unsigned sw = (unsigned)(r * 128 + ((chb ^ (r & 7)) << 4));
                unsigned r0, r1, r2, r3;
                ldsm4(r0, r1, r2, r3, sb + XH + sw);
                bh[2 * ng][0] = r0; bh[2 * ng][1] = r1;
                bh[2 * ng + 1][0] = r2; bh[2 * ng + 1][1] = r3;
                ldsm4(r0, r1, r2, r3, sb + XL + sw);
                bl[2 * ng][0] = r0; bl[2 * ng][1] = r1;
                bl[2 * ng + 1][0] = r2; bl[2 * ng + 1][1] = r3;
            }
#pragma unroll
            for (int mi = 0; mi < 2; mi++) {
                long ab = (long)(tap * 32 + mi * 16 + arow) * 64 + k16 * 16 + acol;
                unsigned ah[4];
                ah[0] = *(const unsigned*)(g_w2ah + ab);
                ah[1] = *(const unsigned*)(g_w2ah + ab + 8 * 64);
                ah[2] = *(const unsigned*)(g_w2ah + ab + 8);
                ah[3] = *(const unsigned*)(g_w2ah + ab + 8 * 64 + 8);
#pragma unroll
                for (int ni = 0; ni < 4; ni++) {
                    mma16816(acc[mi][ni], ah, bh[ni]);
                    mma16816(acc[mi][ni], ah, bl[ni]);
                }
                ah[0] = *(const unsigned*)(g_w2al + ab);
                ah[1] = *(const unsigned*)(g_w2al + ab + 8 * 64);
                ah[2] = *(const unsigned*)(g_w2al + ab + 8);
                ah[3] = *(const unsigned*)(g_w2al + ab + 8 * 64 + 8);
#pragma unroll
                for (int ni = 0; ni < 4; ni++)
                    mma16816(acc[mi][ni], ah, bh[ni]);
            }
        }
    }

#pragma unroll
    for (int mi = 0; mi < 2; mi++) {
        int oc0 = mi * 16 + (lane >> 2);
        float bias0 = ba[oc0], bias1 = ba[oc0 + 8];
#pragma unroll
        for (int ni = 0; ni < 4; ni++) {
            int t0 = n_base + ni * 8 + (lane & 3) * 2;
#pragma unroll
            for (int q = 0; q < 4; q++) {
                int oc = (q < 2) ? oc0 : oc0 + 8;
                float v = fmaxf(acc[mi][ni][q] + ((q < 2) ? bias0 : bias1), 0.f);
                int t = t0 + (q & 1);
                long base = (long)b * 16384 + t * 64 + oc;
                __nv_bfloat16 h = __float2bfloat16(v);
                g_c2h[base] = h;
                g_c2l[base] = __float2bfloat16(v - __bfloat162float(h));
            }
        }
    }
}

// ======================= Layer 2 kNN branch (mma M-table, fp32 distances) =======
// smem: ss fp32 [n][66] 16896 | sn 256 | region @17152:
//   phase 1: Sh 8192 | Sl 8192 ; phase 2: Mt [(k*64+n)][36] 82944 (aliased)
__global__ __launch_bounds__(288, 2) void k_l2_knn(const int* __restrict__ idx,
                                                   const float* __restrict__ bb) {
    extern __shared__ __align__(16) char smem[];
    unsigned sb = smem_u32(smem);
    float* ss = (float*)smem;
    float* sn = (float*)(smem + 16896);
    const unsigned SH = 17152, SL = 17152 + 8192;
    float* Mt = (float*)(smem + 17152);
    int b = blockIdx.x, tid = threadIdx.x, lane = tid & 31, wid = tid >> 5;

    for (int i = tid; i < 4096; i += 288) {
        int n = i & 63, c = i >> 6;
        ss[n * 66 + c] = g_out1[(b * 64 + c) * 256 + idx[n]];
    }
    __syncthreads();
    for (int i = tid; i < 2048; i += 288) {
        int n = i >> 5, cp = (i & 31) * 2;
        float f0 = ss[n * 66 + cp], f1 = ss[n * 66 + cp + 1];
        int ch = cp >> 3;
        unsigned off = (unsigned)(n * 128 + ((ch ^ (n & 7)) << 4) + (cp & 7) * 2);
        __nv_bfloat16 h0 = __float2bfloat16(f0), h1 = __float2bfloat16(f1);
        *(unsigned*)(smem + SH + off) = pkbf(f0, f1);
        *(unsigned*)(smem + SL + off) =
            pkbf(f0 - __bfloat162float(h0), f1 - __bfloat162float(h1));
    }
    if (tid < 64) {
        float s = 0.f;
#pragma unroll 16
        for (int c = 0; c < 64; c++) { float v = ss[tid * 66 + c]; s += v * v; }
        sn[tid] = s;
    }
    __syncthreads();

    int ri = lane & 7, mat = lane >> 3;
    float acc[2][8][4];
#pragma unroll
    for (int i = 0; i < 2; i++)
#pragma unroll
        for (int j = 0; j < 8; j++)
#pragma unroll
            for (int q = 0; q < 4; q++) acc[i][j][q] = 0.f;

    {
        int w = wid;
        int arow = (lane >> 2), acol = (lane & 3) * 2;
#pragma unroll
        for (int k16 = 0; k16 < 4; k16++) {
#pragma unroll
            for (int half = 0; half < 2; half++) {
                unsigned bh[4][2], bl[4][2];
                int chb = k16 * 2 + (mat & 1);
#pragma unroll
                for (int ng = 0; ng < 2; ng++) {
                    int row = half * 32 + ng * 16 + ri + ((mat >> 1) << 3);
                    unsigned sw = (unsigned)(row * 128 + ((chb ^ (row & 7)) << 4));
                    unsigned r0, r1, r2, r3;
                    ldsm4(r0, r1, r2, r3, sb + SH + sw);
                    bh[2 * ng][0] = r0; bh[2 * ng][1] = r1;
                    bh[2 * ng + 1][0] = r2; bh[2 * ng + 1][1] = r3;
                    ldsm4(r0, r1, r2, r3, sb + SL + sw);
                    bl[2 * ng][0] = r0; bl[2 * ng][1] = r1;
                    bl[2 * ng + 1][0] = r2; bl[2 * ng + 1][1] = r3;
                }
#pragma unroll
                for (int mi = 0; mi < 2; mi++) {
                    long wbase = (long)(w * 32 + mi * 16 + arow) * 64 + k16 * 16 + acol;
                    unsigned ah[4];
                    ah[0] = *(const unsigned*)(g_w2bh + wbase);
                    ah[1] = *(const unsigned*)(g_w2bh + wbase + 8 * 64);
                    ah[2] = *(const unsigned*)(g_w2bh + wbase + 8);
                    ah[3] = *(const unsigned*)(g_w2bh + wbase + 8 * 64 + 8);
#pragma unroll
                    for (int nj = 0; nj < 4; nj++) {
                        mma16816(acc[mi][half * 4 + nj], ah, bh[nj]);
                        mma16816(acc[mi][half * 4 + nj], ah, bl[nj]);
                    }
                    ah[0] = *(const unsigned*)(g_w2bl + wbase);
                    ah[1] = *(const unsigned*)(g_w2bl + wbase + 8 * 64);
                    ah[2] = *(const unsigned*)(g_w2bl + wbase + 8);
                    ah[3] = *(const unsigned*)(g_w2bl + wbase + 8 * 64 + 8);
#pragma unroll
                    for (int nj = 0; nj < 4; nj++)
                        mma16816(acc[mi][half * 4 + nj], ah, bh[nj]);
                }
            }
        }
    }
    __syncthreads();

    {
        int w = wid;
#pragma unroll
        for (int mi = 0; mi < 2; mi++) {
            int oc0 = mi * 16 + (lane >> 2);
#pragma unroll
            for (int nj = 0; nj < 8; nj++) {
                int n0 = nj * 8 + (lane & 3) * 2;
#pragma unroll
                for (int q = 0; q < 4; q++) {
                    int oc = (q < 2) ? oc0 : oc0 + 8;
                    int n = n0 + (q & 1);
                    Mt[(w * 64 + n) * 36 + oc] = acc[mi][nj][q];
                }
            }
        }
    }
    __syncthreads();

    if (tid < 256) {
        int t = tid;
        ull xr2[32]; float xn = 0.f;
#pragma unroll
        for (int c2 = 0; c2 < 32; c2++) {
            float f0 = g_out1[(b * 64 + 2 * c2) * 256 + t];
            float f1 = g_out1[(b * 64 + 2 * c2 + 1) * 256 + t];
            xn += f0 * f0 + f1 * f1;
            xr2[c2] = pack2(f0, f1);
        }

        float bd[9]; int bi[9];
#pragma unroll
        for (int k = 0; k < 9; k++) { bd[k] = 3.0e38f; bi[k] = 0; }
        for (int n = 0; n < 64; n++) {
            const ull* sp = (const ull*)&ss[n * 66];
            ull d2 = 0ull;
#pragma unroll
            for (int j = 0; j < 32; j++) fma2(d2, xr2[j], sp[j]);
            float2 dv = unpk(d2);
            float d = xn + sn[n] - 2.f * (dv.x + dv.y);
            if (d < bd[8]) {
                bool placed = false;
#pragma unroll
                for (int j = 8; j > 0; --j) {
                    if (!placed) {
                        if (d < bd[j - 1]) { bd[j] = bd[j - 1]; bi[j] = bi[j - 1]; }
                        else { bd[j] = d; bi[j] = n; placed = true; }
                    }
                }
                if (!placed) { bd[0] = d; bi[0] = n; }
            }
        }

#pragma unroll
        for (int half = 0; half < 2; half++) {
            float acm[16];
#pragma unroll
            for (int o = 0; o < 16; o++) acm[o] = bb[half * 16 + o];
#pragma unroll
            for (int k = 0; k < 9; k++) {
                const float4* m4 = (const float4*)&Mt[(k * 64 + bi[k]) * 36 + half * 16];
                float4 v0 = m4[0], v1 = m4[1], v2 = m4[2], v3 = m4[3];
                acm[0] += v0.x; acm[1] += v0.y; acm[2] += v0.z; acm[3] += v0.w;
                acm[4] += v1.x; acm[5] += v1.y; acm[6] += v1.z; acm[7] += v1.w;
                acm[8] += v2.x; acm[9] += v2.y; acm[10] += v2.z; acm[11] += v2.w;
                acm[12] += v3.x; acm[13] += v3.y; acm[14] += v3.z; acm[15] += v3.w;
            }
#pragma unroll
            for (int j = 0; j < 8; j++)
                c2_store((long)b * 16384 + t * 64 + 32 + half * 16 + 2 * j,
                         fmaxf(acm[2 * j], 0.f), fmaxf(acm[2 * j + 1], 0.f));
        }
    }
}

// ======== Layer 2 pw as bf16 split mma: C[128][256] = W[128x64] * cat2 ==========
__global__ __launch_bounds__(256) void k_l2_pw(const float* __restrict__ bp) {
    extern __shared__ __align__(16) char smem[];
    unsigned sb = smem_u32(smem);
    int b = blockIdx.x, tid = threadIdx.x, lane = tid & 31, warp = tid >> 5;

#pragma unroll
    for (int j = 0; j < 8; j++) {
        int q = tid + j * 256;
        int row = q >> 3, ch = q & 7;
        unsigned dst = sb + row * 128 + ((ch ^ (row & 7)) << 4);
        cpa16(dst, g_c2h + (long)b * 16384 + row * 64 + ch * 8);
        cpa16(dst + 32768, g_c2l + (long)b * 16384 + row * 64 + ch * 8);
    }
#pragma unroll
    for (int j = 0; j < 4; j++) {
        int q = tid + j * 256;
        int row = q >> 3, ch = q & 7;
        unsigned dst = sb + 65536 + row * 128 + ((ch ^ (row & 7)) << 4);
        cpa16(dst, g_wph + row * 64 + ch * 8);
        cpa16(dst + 16384, g_wpl + row * 64 + ch * 8);
    }
    cpa_commit();
    cpa_wait0();
    __syncthreads();

    int m_base = (warp & 1) * 64;
    int n_base = (warp >> 1) * 64;
    int ri = lane & 7, mat = lane >> 3;

    float acc[4][8][4];
#pragma unroll
    for (int i = 0; i < 4; i++)
#pragma unroll
        for (int j = 0; j < 8; j++)
#pragma unroll
            for (int q = 0; q < 4; q++) acc[i][j][q] = 0.f;

#pragma unroll
    for (int kk = 0; kk < 4; kk++) {
        unsigned af[4][4], bh[8][2], bl[8][2];
#pragma unroll
        for (int ng = 0; ng < 4; ng++) {
            int row = n_base + ng * 16 + ri + ((mat >> 1) << 3);
            int ch = kk * 2 + (mat & 1);
            unsigned bd_ = sb + row * 128 + ((ch ^ (row & 7)) << 4);
            unsigned r0, r1, r2, r3;
            ldsm4(r0, r1, r2, r3, bd_);
            bh[2 * ng][0] = r0; bh[2 * ng][1] = r1;
            bh[2 * ng + 1][0] = r2; bh[2 * ng + 1][1] = r3;
            ldsm4(r0, r1, r2, r3, bd_ + 32768);
            bl[2 * ng][0] = r0; bl[2 * ng][1] = r1;
            bl[2 * ng + 1][0] = r2; bl[2 * ng + 1][1] = r3;
        }
#pragma unroll
        for (int mi = 0; mi < 4; mi++) {
            int row = m_base + mi * 16 + ri + ((mat & 1) << 3);
            int ch = kk * 2 + (mat >> 1);
            unsigned ad = sb + 65536 + row * 128 + ((ch ^ (row & 7)) << 4);
            ldsm4(af[mi][0], af[mi][1], af[mi][2], af[mi][3], ad);
        }
#pragma unroll
        for (int mi = 0; mi < 4; mi++)
#pragma unroll
            for (int ni = 0; ni < 8; ni++) {
                mma16816(acc[mi][ni], af[mi], bh[ni]);
                mma16816(acc[mi][ni], af[mi], bl[ni]);
            }
#pragma unroll
        for (int mi = 0; mi < 4; mi++) {
            int row = m_base + mi * 16 + ri + ((mat & 1) << 3);
            int ch = kk * 2 + (mat >> 1);
            unsigned ad = sb + 81920 + row * 128 + ((ch ^ (row & 7)) << 4);
            ldsm4(af[mi][0], af[mi][1], af[mi][2], af[mi][3], ad);
        }
#pragma unroll
        for (int mi = 0; mi < 4; mi++)
#pragma unroll
            for (int ni = 0; ni < 8; ni++)
                mma16816(acc[mi][ni], af[mi], bh[ni]);
    }

#pragma unroll
    for (int mi = 0; mi < 4; mi++) {
        int oc0 = m_base + mi * 16 + (lane >> 2);
        float bias0 = bp[oc0], bias1 = bp[oc0 + 8];
#pragma unroll
        for (int ni = 0; ni < 8; ni++) {
            int t0 = n_base + ni * 8 + (lane & 3) * 2;
#pragma unroll
            for (int q = 0; q < 4; q++) {
                int oc = (q < 2) ? oc0 : oc0 + 8;
                float v = acc[mi][ni][q] + ((q < 2) ? bias0 : bias1);
                int t = t0 + (q & 1);
                int cp = oc >> 2, ii = (oc >> 1) & 1, jj = oc & 1;
                int h = t >> 4, w = t & 15;
                long pos = (long)b * 32768 + cp * 1024 + (2 * h + ii) * 32 + 2 * w + jj;
                __nv_bfloat16 hi = __float2bfloat16(v);
                g_ahi[pos] = hi;
                g_alo[pos] = __float2bfloat16(v - __bfloat162float(hi));
            }
        }
    }
}

// ======================= fc1: bf16 split GEMM, 3-stage pipeline =================
__global__ __launch_bounds__(512) void k_fc1t(const float* __restrict__ W) {
    extern __shared__ __align__(16) char smem[];
    unsigned sbase = smem_u32(smem);
    int tid = threadIdx.x, lane = tid & 31, warp = tid >> 5;
    int n0 = blockIdx.x * 128, sk = blockIdx.z;
    long kbase = (long)sk * 2048;

    int m_base = (warp & 3) * 64;
    int n_base = (warp >> 2) * 32;

    int aq[2], ac[2];
#pragma unroll
    for (int j = 0; j < 2; j++) { int q = tid + j * 512; aq[j] = q >> 2; ac[j] = q & 3; }
    int wr = tid >> 2, wc = tid & 3;

    float acc[4][4][4];
#pragma unroll
    for (int i = 0; i < 4; i++)
#pragma unroll
        for (int j = 0; j < 4; j++)
#pragma unroll
            for (int q = 0; q < 4; q++) acc[i][j][q] = 0.f;

    const float* wgp = W + (long)(n0 + wr) * 32768 + kbase + wc * 8;

    float4 wa0 = *(const float4*)(wgp), wb0 = *(const float4*)(wgp + 4);
    float4 wa1 = *(const float4*)(wgp + 32), wb1 = *(const float4*)(wgp + 36);
#pragma unroll
    for (int j = 0; j < 2; j++) {
        int r = aq[j], c = ac[j];
        unsigned sw = (unsigned)(r * 64 + ((c ^ ((r >> 1) & 3)) << 4));
        cpa16(sbase + sw, g_ahi + (long)r * 32768 + kbase + c * 8);
        cpa16(sbase + 16384 + sw, g_alo + (long)r * 32768 + kbase + c * 8);
    }
    cpa_commit();
#pragma unroll
    for (int j = 0; j < 2; j++) {
        int r = aq[j], c = ac[j];
        unsigned sw = (unsigned)(r * 64 + ((c ^ ((r >> 1) & 3)) << 4));
        cpa16(sbase + 49152 + sw, g_ahi + (long)r * 32768 + kbase + 32 + c * 8);
        cpa16(sbase + 49152 + 16384 + sw, g_alo + (long)r * 32768 + kbase + 32 + c * 8);
    }
    cpa_commit();
    wsplit_store(sbase + 32768, wr, wc, wa0, wb0);
    wsplit_store(sbase + 49152 + 32768, wr, wc, wa1, wb1);

    int ri = lane & 7, mat = lane >> 3;

    for (int it = 0; it < 64; it++) {
        unsigned stb = sbase + (unsigned)(it % 3) * 49152u;
        cpa_wait1();
        __syncthreads();

        float4 wna, wnb;
        unsigned nb = sbase + (unsigned)((it + 2) % 3) * 49152u;
        if (it < 62) {
            long ko = kbase + (it + 2) * 32;
            wna = *(const float4*)(wgp + (it + 2) * 32);
            wnb = *(const float4*)(wgp + (it + 2) * 32 + 4);
#pragma unroll
            for (int j = 0; j < 2; j++) {
                int r = aq[j], c = ac[j];
                unsigned sw = (unsigned)(r * 64 + ((c ^ ((r >> 1) & 3)) << 4));
                cpa16(nb + sw, g_ahi + (long)r * 32768 + ko + c * 8);
                cpa16(nb + 16384 + sw, g_alo + (long)r * 32768 + ko + c * 8);
            }
        }
        cpa_commit();

#pragma unroll
        for (int k16 = 0; k16 < 2; k16++) {
            unsigned af[4][4], bh[4][2], bl[4][2];
#pragma unroll
            for (int ng = 0; ng < 2; ng++) {
                int row = n_base + ng * 16 + ri + ((mat >> 1) << 3);
                int c = k16 * 2 + (mat & 1);
                unsigned bd_ = stb + 32768 + row * 64 + ((c ^ ((row >> 1) & 3)) << 4);
                unsigned r0, r1, r2, r3;
                ldsm4(r0, r1, r2, r3, bd_);
                bh[2 * ng][0] = r0; bh[2 * ng][1] = r1;
                bh[2 * ng + 1][0] = r2; bh[2 * ng + 1][1] = r3;
                ldsm4(r0, r1, r2, r3, bd_ + 8192);
                bl[2 * ng][0] = r0; bl[2 * ng][1] = r1;
                bl[2 * ng + 1][0] = r2; bl[2 * ng + 1][1] = r3;
            }
#pragma unroll
            for (int mi = 0; mi < 4; mi++) {
                int row = m_base + mi * 16 + ri + ((mat & 1) << 3);
                int c = k16 * 2 + (mat >> 1);
                unsigned ad = stb + row * 64 + ((c ^ ((row >> 1) & 3)) << 4);
                ldsm4(af[mi][0], af[mi][1], af[mi][2], af[mi][3], ad);
            }
#pragma unroll
            for (int mi = 0; mi < 4; mi++)
#pragma unroll
                for (int ni = 0; ni < 4; ni++) {
                    mma16816(acc[mi][ni], af[mi], bh[ni]);
                    mma16816(acc[mi][ni], af[mi], bl[ni]);
                }
#pragma unroll
            for (int mi = 0; mi < 4; mi++) {
                int row = m_base + mi * 16 + ri + ((mat & 1) << 3);
                int c = k16 * 2 + (mat >> 1);
                unsigned ad = stb + 16384 + row * 64 + ((c ^ ((row >> 1) & 3)) << 4);
                ldsm4(af[mi][0], af[mi][1], af[mi][2], af[mi][3], ad);
            }
#pragma unroll
            for (int mi = 0; mi < 4; mi++)
#pragma unroll
                for (int ni = 0; ni < 4; ni++)
                    mma16816(acc[mi][ni], af[mi], bh[ni]);
        }

        if (it < 62)
            wsplit_store(nb + 32768, wr, wc, wna, wnb);
    }

    float* slab = g_fc1p + (long)sk * BATCH * 1024;
#pragma unroll
    for (int mi = 0; mi < 4; mi++)
#pragma unroll
        for (int ni = 0; ni < 4; ni++) {
            int m = m_base + mi * 16 + (lane >> 2);
            int n = n0 + n_base + ni * 8 + (lane & 3) * 2;
            *(float2*)&slab[(long)m * 1024 + n] =
                make_float2(acc[mi][ni][0], acc[mi][ni][1]);
            *(float2*)&slab[(long)(m + 8) * 1024 + n] =
                make_float2(acc[mi][ni][2], acc[mi][ni][3]);
        }
}

// ======================= fc2 (fused slab-reduce + relu + fc2) ===================
__global__ __launch_bounds__(256) void k_fc2(const float* __restrict__ fc1b,
                                             const float* __restrict__ w2,
                                             const float* __restrict__ b2,
                                             float* __restrict__ out) {
    __shared__ __align__(16) float hs[1024];
    __shared__ float red[10 * 256];
    int b = blockIdx.x, tid = threadIdx.x;
    for (int j = tid; j < 1024; j += 256) {
        float s = 0.f;
#pragma unroll
        for (int q = 0; q < 16; q++) s += g_fc1p[(long)q * BATCH * 1024 + b * 1024 + j];
        hs[j] = fmaxf(s + fc1b[j], 0.f);
    }
    __syncthreads();
    float p[10];
#pragma unroll
    for (int n = 0; n < 10; n++) p[n] = 0.f;
    for (int j = tid; j < 1024; j += 256) {
        float hv = hs[j];
#pragma unroll
        for (int n = 0; n < 10; n++) p[n] += hv * w2[n * 1024 + j];
    }
#pragma unroll
    for (int n = 0; n < 10; n++) red[n * 256 + tid] = p[n];
    __syncthreads();
    for (int s = 128; s > 0; s >>= 1) {
        if (tid < s) {
#pragma unroll
            for (int n = 0; n < 10; n++) red[n * 256 + tid] += red[n * 256 + tid + s];
        }
        __syncthreads();
    }
    if (tid < 10) out[b * 10 + tid] = red[tid * 256] + b2[tid];
}

// =================================================================================
extern "C" void kernel_launch(void* const* d_in, const int* in_sizes, int n_in,
                              void* d_out, int out_size) {
    const float* x    = (const float*)d_in[0];
    const int*   idx1 = (const int*)d_in[1];
    const int*   idx2 = (const int*)d_in[2];
    const float* w1a  = (const float*)d_in[3];
    const float* b1a  = (const float*)d_in[4];
    const float* w1b  = (const float*)d_in[5];
    const float* b1b  = (const float*)d_in[6];
    const float* w1p  = (const float*)d_in[7];
    const float* b1p  = (const float*)d_in[8];
    const float* w2a  = (const float*)d_in[9];
    const float* b2a  = (const float*)d_in[10];
    const float* w2b  = (const float*)d_in[11];
    const float* b2b  = (const float*)d_in[12];
    const float* w2p  = (const float*)d_in[13];
    const float* b2p  = (const float*)d_in[14];
    const float* fc1w = (const float*)d_in[15];
    const float* fc1b = (const float*)d_in[16];
    const float* fc2w = (const float*)d_in[17];
    const float* fc2b = (const float*)d_in[18];
    float* out = (float*)d_out;

    const int smem_l2c  = 66048;
    const int smem_knn  = 100096;
    const int smem_pw   = 98304;
    const int smem_fc1t = 147456;
    cudaFuncSetAttribute(k_l2c,    cudaFuncAttributeMaxDynamicSharedMemorySize, smem_l2c);
    cudaFuncSetAttribute(k_l2_knn, cudaFuncAttributeMaxDynamicSharedMemorySize, smem_knn);
    cudaFuncSetAttribute(k_l2_pw,  cudaFuncAttributeMaxDynamicSharedMemorySize, smem_pw);
    cudaFuncSetAttribute(k_fc1t,   cudaFuncAttributeMaxDynamicSharedMemorySize, smem_fc1t);

    k_repack<<<72, 256>>>(w1a, w1b, w2a, w2b, w2p);
    k_l1<<<dim3(BATCH, 2), 128>>>(x, idx1, b1a, b1b, w1p, b1p);
    k_l2_knn<<<BATCH, 288, smem_knn>>>(idx2, b2b);
    k_l2c<<<BATCH, 256, smem_l2c>>>(b2a);
    k_l2_pw<<<BATCH, 256, smem_pw>>>(b2p);
    k_fc1t<<<dim3(8, 1, 16), 512, smem_fc1t>>>(fc1w);
    k_fc2<<<BATCH, 256>>>(fc1b, fc2w, fc2b, out);
}

// round 16
// speedup vs baseline: 1.0946x; 1.0946x over previous
#include <cuda_runtime.h>
#include <cuda_bf16.h>

typedef unsigned long long ull;
constexpr int BATCH = 256;

// ---------------- scratch (device globals) ----------------
__device__ __align__(16) float g_out1[BATCH * 64 * 256];
__device__ __align__(16) float g_fc1p[16 * BATCH * 1024];
__device__ __align__(16) float g_r1a[1728];
__device__ __align__(16) float g_r1b[1728];
__device__ __align__(16) __nv_bfloat16 g_o1h[BATCH * 16384];  // out1 hi [t][c]
__device__ __align__(16) __nv_bfloat16 g_o1l[BATCH * 16384];
__device__ __align__(16) __nv_bfloat16 g_w2ah[9 * 32 * 64];   // conv W [tap][oc][c]
__device__ __align__(16) __nv_bfloat16 g_w2al[9 * 32 * 64];
__device__ __align__(16) __nv_bfloat16 g_w2bh[9 * 32 * 64];   // knn W [tap][oc][c]
__device__ __align__(16) __nv_bfloat16 g_w2bl[9 * 32 * 64];
__device__ __align__(16) __nv_bfloat16 g_c2h[BATCH * 16384];  // cat2 hi [t][c]
__device__ __align__(16) __nv_bfloat16 g_c2l[BATCH * 16384];
__device__ __align__(16) __nv_bfloat16 g_wph[8192];           // w2p hi [oc][c]
__device__ __align__(16) __nv_bfloat16 g_wpl[8192];
__device__ __align__(16) __nv_bfloat16 g_ahi[BATCH * 32768];
__device__ __align__(16) __nv_bfloat16 g_alo[BATCH * 32768];

// ---------------- f32x2 helpers ----------------
__device__ __forceinline__ ull pack2(float lo, float hi) {
    ull r;
    asm("mov.b64 %0, {%1, %2};" : "=l"(r) : "r"(__float_as_uint(lo)), "r"(__float_as_uint(hi)));
    return r;
}
__device__ __forceinline__ ull packd(float s) { return pack2(s, s); }
__device__ __forceinline__ void fma2(ull& d, ull a, ull b) {
    asm("fma.rn.f32x2 %0, %1, %2, %3;" : "=l"(d) : "l"(a), "l"(b), "l"(d));
}
__device__ __forceinline__ float2 unpk(ull v) {
    unsigned lo, hi;
    asm("mov.b64 {%0, %1}, %2;" : "=r"(lo), "=r"(hi) : "l"(v));
    float2 f; f.x = __uint_as_float(lo); f.y = __uint_as_float(hi);
    return f;
}

// ---------------- mma.sync helpers ----------------
__device__ __forceinline__ unsigned smem_u32(const void* p) {
    unsigned a;
    asm("{ .reg .u64 t; cvta.to.shared.u64 t, %1; cvt.u32.u64 %0, t; }" : "=r"(a) : "l"(p));
    return a;
}
__device__ __forceinline__ void ldsm4(unsigned& r0, unsigned& r1, unsigned& r2, unsigned& r3,
                                      unsigned addr) {
    asm volatile("ldmatrix.sync.aligned.m8n8.x4.shared.b16 {%0,%1,%2,%3}, [%4];"
                 : "=r"(r0), "=r"(r1), "=r"(r2), "=r"(r3) : "r"(addr));
}
__device__ __forceinline__ void mma16816(float* c, const unsigned* a, const unsigned* b) {
    asm volatile(
        "mma.sync.aligned.m16n8k16.row.col.f32.bf16.bf16.f32 "
        "{%0,%1,%2,%3},{%4,%5,%6,%7},{%8,%9},{%0,%1,%2,%3};"
        : "+f"(c[0]), "+f"(c[1]), "+f"(c[2]), "+f"(c[3])
        : "r"(a[0]), "r"(a[1]), "r"(a[2]), "r"(a[3]), "r"(b[0]), "r"(b[1]));
}
__device__ __forceinline__ void cpa16(unsigned dst, const void* src) {
    asm volatile("cp.async.cg.shared.global [%0], [%1], 16;" :: "r"(dst), "l"(src));
}
__device__ __forceinline__ void cpa_commit() { asm volatile("cp.async.commit_group;"); }
__device__ __forceinline__ void cpa_wait0() {
    asm volatile("cp.async.wait_group 0;" ::: "memory");
}
__device__ __forceinline__ void cpa_wait1() {
    asm volatile("cp.async.wait_group 1;" ::: "memory");
}
__device__ __forceinline__ void sts128(unsigned addr, uint4 v) {
    asm volatile("st.shared.v4.b32 [%0], {%1,%2,%3,%4};"
                 :: "r"(addr), "r"(v.x), "r"(v.y), "r"(v.z), "r"(v.w));
}
__device__ __forceinline__ unsigned pkbf(float a, float b) {
    __nv_bfloat16 ha = __float2bfloat16(a), hb = __float2bfloat16(b);
    return ((unsigned)__bfloat16_as_ushort(hb) << 16) | __bfloat16_as_ushort(ha);
}
__device__ __forceinline__ void wsplit_store(unsigned hi_base, int row, int c,
                                             float4 a, float4 b) {
    unsigned sw = (unsigned)(row * 64 + ((c ^ ((row >> 1) & 3)) << 4));
    uint4 hi, lo;
    hi.x = pkbf(a.x, a.y); hi.y = pkbf(a.z, a.w);
    hi.z = pkbf(b.x, b.y); hi.w = pkbf(b.z, b.w);
    __nv_bfloat16 t0 = __float2bfloat16(a.x), t1 = __float2bfloat16(a.y);
    __nv_bfloat16 t2 = __float2bfloat16(a.z), t3 = __float2bfloat16(a.w);
    __nv_bfloat16 t4 = __float2bfloat16(b.x), t5 = __float2bfloat16(b.y);
    __nv_bfloat16 t6 = __float2bfloat16(b.z), t7 = __float2bfloat16(b.w);
    lo.x = pkbf(a.x - __bfloat162float(t0), a.y - __bfloat162float(t1));
    lo.y = pkbf(a.z - __bfloat162float(t2), a.w - __bfloat162float(t3));
    lo.z = pkbf(b.x - __bfloat162float(t4), b.y - __bfloat162float(t5));
    lo.w = pkbf(b.z - __bfloat162float(t6), b.w - __bfloat162float(t7));
    sts128(hi_base + sw, hi);
    sts128(hi_base + 8192 + sw, lo);
}
__device__ __forceinline__ void c2_store(long base, float r0, float r1) {
    __nv_bfloat16 h0 = __float2bfloat16(r0), h1 = __float2bfloat16(r1);
    *(unsigned*)&g_c2h[base] = pkbf(r0, r1);
    *(unsigned*)&g_c2l[base] = pkbf(r0 - __bfloat162float(h0), r1 - __bfloat162float(h1));
}

// ---------------- weight repack ----------------
__global__ __launch_bounds__(256) void k_repack(const float* __restrict__ w1a,
                                                const float* __restrict__ w1b,
                                                const float* __restrict__ w2a,
                                                const float* __restrict__ w2b,
                                                const float* __restrict__ w2p) {
    int i = blockIdx.x * 256 + threadIdx.x;
    if (i < 1728) {
        int oc = i / 108, rest = i % 108;
        g_r1a[rest * 16 + oc] = w1a[i];
        g_r1b[rest * 16 + oc] = w1b[i];
    }
    if (i < 8192) {
        float v = w2p[i];
        __nv_bfloat16 h = __float2bfloat16(v);
        g_wph[i] = h;
        g_wpl[i] = __float2bfloat16(v - __bfloat162float(h));
    }
    if (i < 18432) {
        int oc = i / 576, rest = i % 576;
        int c = rest / 9, k = rest % 9;
        float va = w2a[i];
        __nv_bfloat16 ha = __float2bfloat16(va);
        g_w2ah[(k * 32 + oc) * 64 + c] = ha;
        g_w2al[(k * 32 + oc) * 64 + c] = __float2bfloat16(va - __bfloat162float(ha));
        float vb = w2b[i];
        __nv_bfloat16 hb = __float2bfloat16(vb);
        g_w2bh[(k * 32 + oc) * 64 + c] = hb;
        g_w2bl[(k * 32 + oc) * 64 + c] = __float2bfloat16(vb - __bfloat162float(hb));
    }
}

// ======================= Layer 1 FUSED, pixel-split x2 ==========================
__global__ __launch_bounds__(128) void k_l1(const float* __restrict__ x,
                                            const int* __restrict__ idx,
                                            const float* __restrict__ b1a,
                                            const float* __restrict__ b1b,
                                            const float* __restrict__ wp,
                                            const float* __restrict__ bp) {
    __shared__ __align__(16) float xs[12 * 256];
    __shared__ __align__(16) float ss[12 * 64];
    __shared__ float sn[64];
    __shared__ __align__(16) float wsa[1728];
    __shared__ __align__(16) float wsb[1728];
    __shared__ __align__(16) float wsp[64 * 32];
    int b = blockIdx.x, tid = threadIdx.x;
    int p = blockIdx.y * 128 + tid;

    for (int i = tid; i < 12 * 256; i += 128) {
        int cu = i >> 8, t = i & 255;
        int h = t >> 4, w = t & 15;
        int c = cu >> 2, ii = (cu >> 1) & 1, jj = cu & 1;
        xs[i] = x[((b * 3 + c) * 32 + (2 * h + ii)) * 32 + 2 * w + jj];
    }
    for (int i = tid; i < 1728; i += 128) { wsa[i] = g_r1a[i]; wsb[i] = g_r1b[i]; }
    for (int i = tid; i < 64 * 32; i += 128) wsp[i] = wp[i];
    __syncthreads();
    for (int i = tid; i < 12 * 64; i += 128)
        ss[i] = xs[(i >> 6) * 256 + idx[i & 63]];
    __syncthreads();
    if (tid < 64) {
        float s = 0.f;
#pragma unroll
        for (int c = 0; c < 12; c++) { float v = ss[c * 64 + tid]; s += v * v; }
        sn[tid] = s;
    }
    __syncthreads();

    int h = p >> 4, w = p & 15;

    ull acv[8];
#pragma unroll
    for (int o = 0; o < 8; o++) acv[o] = pack2(b1a[2 * o], b1a[2 * o + 1]);
    for (int c = 0; c < 12; c++) {
        float pp[9];
#pragma unroll
        for (int dy = 0; dy < 3; dy++)
#pragma unroll
            for (int dx = 0; dx < 3; dx++) {
                int y = h + dy - 1, xq = w + dx - 1;
                pp[dy * 3 + dx] = (y >= 0 && y < 16 && xq >= 0 && xq < 16)
                                      ? xs[c * 256 + y * 16 + xq] : 0.f;
            }
#pragma unroll
        for (int tap = 0; tap < 9; tap++) {
            ull s2 = packd(pp[tap]);
            const longlong2* wv = (const longlong2*)&wsa[(c * 9 + tap) * 16];
#pragma unroll
            for (int q = 0; q < 4; q++) {
                longlong2 w4 = wv[q];
                fma2(acv[q * 2 + 0], s2, (ull)w4.x);
                fma2(acv[q * 2 + 1], s2, (ull)w4.y);
            }
        }
    }

    float xr[12]; float xn = 0.f;
#pragma unroll
    for (int c = 0; c < 12; c++) { float v = xs[c * 256 + p]; xr[c] = v; xn += v * v; }

    float bd[9]; int bi[9];
#pragma unroll
    for (int k = 0; k < 9; k++) { bd[k] = 3.0e38f; bi[k] = 0; }
    for (int n = 0; n < 64; n++) {
        float dot = 0.f;
#pragma unroll
        for (int c = 0; c < 12; c++) dot += xr[c] * ss[c * 64 + n];
        float d = xn + sn[n] - 2.f * dot;
        if (d < bd[8]) {
            bool placed = false;
#pragma unroll
            for (int j = 8; j > 0; --j) {
                if (!placed) {
                    if (d < bd[j - 1]) { bd[j] = bd[j - 1]; bi[j] = bi[j - 1]; }
                    else { bd[j] = d; bi[j] = n; placed = true; }
                }
            }
            if (!placed) { bd[0] = d; bi[0] = n; }
        }
    }

    ull akn[8];
#pragma unroll
    for (int o = 0; o < 8; o++) akn[o] = pack2(b1b[2 * o], b1b[2 * o + 1]);
#pragma unroll
    for (int c = 0; c < 12; c++) {
#pragma unroll
        for (int k = 0; k < 9; k++) {
            ull s2 = packd(ss[c * 64 + bi[k]]);
            const longlong2* wv = (const longlong2*)&wsb[(c * 9 + k) * 16];
#pragma unroll
            for (int q = 0; q < 4; q++) {
                longlong2 w4 = wv[q];
                fma2(akn[q * 2 + 0], s2, (ull)w4.x);
                fma2(akn[q * 2 + 1], s2, (ull)w4.y);
            }
        }
    }

    ull xv[16];
#pragma unroll
    for (int o = 0; o < 8; o++) {
        float2 v = unpk(acv[o]);
        xv[o] = pack2(fmaxf(v.x, 0.f), fmaxf(v.y, 0.f));
        float2 u = unpk(akn[o]);
        xv[8 + o] = pack2(fmaxf(u.x, 0.f), fmaxf(u.y, 0.f));
    }
    float vb[8];
    for (int oc = 0; oc < 64; oc++) {
        ull a2 = 0ull;
        const longlong2* wv = (const longlong2*)&wsp[oc * 32];
#pragma unroll
        for (int q = 0; q < 8; q++) {
            longlong2 w4 = wv[q];
            fma2(a2, xv[q * 2 + 0], (ull)w4.x);
            fma2(a2, xv[q * 2 + 1], (ull)w4.y);
        }
        float2 v = unpk(a2);
        float val = v.x + v.y + bp[oc];
        g_out1[(b * 64 + oc) * 256 + p] = val;
        vb[oc & 7] = val;
        if ((oc & 7) == 7) {
            uint4 hi, lo;
            hi.x = pkbf(vb[0], vb[1]); hi.y = pkbf(vb[2], vb[3]);
            hi.z = pkbf(vb[4], vb[5]); hi.w = pkbf(vb[6], vb[7]);
            float l[8];
#pragma unroll
            for (int j = 0; j < 8; j++)
                l[j] = vb[j] - __bfloat162float(__float2bfloat16(vb[j]));
            lo.x = pkbf(l[0], l[1]); lo.y = pkbf(l[2], l[3]);
            lo.z = pkbf(l[4], l[5]); lo.w = pkbf(l[6], l[7]);
            long base = (long)b * 16384 + p * 64 + (oc - 7);
            *(uint4*)&g_o1h[base] = hi;
            *(uint4*)&g_o1l[base] = lo;
        }
    }
}

// ========== Layer 2 conv 3x3: implicit-GEMM mma, persistent over 2 images =======
// smem: Xh 33024 | Xl 33024 | Ah 36864 | Al 36864 = 139776 B. Grid 128.
__global__ __launch_bounds__(256) void k_l2c(const float* __restrict__ ba) {
    extern __shared__ __align__(16) char smem[];
    unsigned sb = smem_u32(smem);
    const unsigned XH = 0, XL = 33024, AH = 66048, AL = 102912;
    int tid = threadIdx.x, lane = tid & 31, warp = tid >> 5;

    // zero row 256 of both X planes (persists; never overwritten)
    if (tid < 16) {
        uint4 z = make_uint4(0, 0, 0, 0);
        unsigned pl = (tid >> 3) ? XL : XH;
        sts128(sb + pl + 256 * 128 + ((tid & 7) << 4), z);
    }
    // weights: staged ONCE for both images
#pragma unroll
    for (int j = 0; j < 9; j++) {
        int q = tid + j * 256;
        int row = q >> 3, ch = q & 7;
        unsigned sw = (unsigned)(row * 128 + ((ch ^ (row & 7)) << 4));
        cpa16(sb + AH + sw, g_w2ah + row * 64 + ch * 8);
        cpa16(sb + AL + sw, g_w2al + row * 64 + ch * 8);
    }
    cpa_commit();

    int n_base = warp * 32;
    int ri = lane & 7, mat = lane >> 3;

    for (int img = 0; img < 2; img++) {
        int b = blockIdx.x * 2 + img;
        __syncthreads();   // img>0: all reads of previous X done before overwrite
#pragma unroll
        for (int j = 0; j < 8; j++) {
            int q = tid + j * 256;
            int row = q >> 3, ch = q & 7;
            unsigned sw = (unsigned)(row * 128 + ((ch ^ (row & 7)) << 4));
            cpa16(sb + XH + sw, g_o1h + (long)b * 16384 + row * 64 + ch * 8);
            cpa16(sb + XL + sw, g_o1l + (long)b * 16384 + row * 64 + ch * 8);
        }
        cpa_commit();
        cpa_wait0();
        __syncthreads();

        float acc[2][4][4];
#pragma unroll
        for (int i = 0; i < 2; i++)
#pragma unroll
            for (int j = 0; j < 4; j++)
#pragma unroll
                for (int q = 0; q < 4; q++) acc[i][j][q] = 0.f;

#pragma unroll
        for (int tap = 0; tap < 9; tap++) {
            int dy = tap / 3, dx = tap % 3;
            int rin[2];
#pragma unroll
            for (int ng = 0; ng < 2; ng++) {
                int t = n_base + ng * 16 + ri + ((mat >> 1) << 3);
                int h = (t >> 4) + dy - 1, w = (t & 15) + dx - 1;
                rin[ng] = ((unsigned)h < 16u && (unsigned)w < 16u) ? h * 16 + w : 256;
            }
#pragma unroll
            for (int k16 = 0; k16 < 4; k16++) {
                unsigned af[2][4], bh[4][2], bl[4][2];
                int chb = k16 * 2 + (mat & 1);
#pragma unroll
                for (int ng = 0; ng < 2; ng++) {
                    int r = rin[ng];
                    unsigned sw = (unsigned)(r * 128 + ((chb ^ (r & 7)) << 4));
                    unsigned r0, r1, r2, r3;
                    ldsm4(r0, r1, r2, r3, sb + XH + sw);
                    bh[2 * ng][0] = r0; bh[2 * ng][1] = r1;
                    bh[2 * ng + 1][0] = r2; bh[2 * ng + 1][1] = r3;
                    ldsm4(r0, r1, r2, r3, sb + XL + sw);
                    bl[2 * ng][0] = r0; bl[2 * ng][1] = r1;
                    bl[2 * ng + 1][0] = r2; bl[2 * ng + 1][1] = r3;
                }
                int cha = k16 * 2 + (mat >> 1);
#pragma unroll
                for (int mi = 0; mi < 2; mi++) {
                    int row = tap * 32 + mi * 16 + ri + ((mat & 1) << 3);
                    unsigned ad = sb + AH + row * 128 + ((cha ^ (row & 7)) << 4);
                    ldsm4(af[mi][0], af[mi][1], af[mi][2], af[mi][3], ad);
                }
#pragma unroll
                for (int mi = 0; mi < 2; mi++)
#pragma unroll
                    for (int ni = 0; ni < 4; ni++) {
                        mma16816(acc[mi][ni], af[mi], bh[ni]);
                        mma16816(acc[mi][ni], af[mi], bl[ni]);
                    }
#pragma unroll
                for (int mi = 0; mi < 2; mi++) {
                    int row = tap * 32 + mi * 16 + ri + ((mat & 1) << 3);
                    unsigned ad = sb + AL + row * 128 + ((cha ^ (row & 7)) << 4);
                    ldsm4(af[mi][0], af[mi][1], af[mi][2], af[mi][3], ad);
                }
#pragma unroll
                for (int mi = 0; mi < 2; mi++)
#pragma unroll
                    for (int ni = 0; ni < 4; ni++)
                        mma16816(acc[mi][ni], af[mi], bh[ni]);
            }
        }

#pragma unroll
        for (int mi = 0; mi < 2; mi++) {
            int oc0 = mi * 16 + (lane >> 2);
            float bias0 = ba[oc0], bias1 = ba[oc0 + 8];
#pragma unroll
            for (int ni = 0; ni < 4; ni++) {
                int t0 = n_base + ni * 8 + (lane & 3) * 2;
#pragma unroll
                for (int q = 0; q < 4; q++) {
                    int oc = (q < 2) ? oc0 : oc0 + 8;
                    float v = fmaxf(acc[mi][ni][q] + ((q < 2) ? bias0 : bias1), 0.f);
                    int t = t0 + (q & 1);
                    long base = (long)b * 16384 + t * 64 + oc;
                    __nv_bfloat16 h = __float2bfloat16(v);
                    g_c2h[base] = h;
                    g_c2l[base] = __float2bfloat16(v - __bfloat162float(h));
                }
            }
        }
    }
}

// ======================= Layer 2 kNN branch (mma M-table, fp32 distances) =======
// smem: ss fp32 [n][66] 16896 | sn 256 | region @17152:
//   phase 1: Sh 8192 | Sl 8192 ; phase 2: Mt [(k*64+n)][36] 82944 (aliased)
__global__ __launch_bounds__(288, 2) void k_l2_knn(const int* __restrict__ idx,
                                                   const float* __restrict__ bb) {
    extern __shared__ __align__(16) char smem[];
    unsigned sb = smem_u32(smem);
    float* ss = (float*)smem;
    float* sn = (float*)(smem + 16896);
    const unsigned SH = 17152, SL = 17152 + 8192;
    float* Mt = (float*)(smem + 17152);
    int b = blockIdx.x, tid = threadIdx.x, lane = tid & 31, wid = tid >> 5;

    for (int i = tid; i < 4096; i += 288) {
        int n = i & 63, c = i >> 6;
        ss[n * 66 + c] = g_out1[(b * 64 + c) * 256 + idx[n]];
    }
    __syncthreads();
    for (int i = tid; i < 2048; i += 288) {
        int n = i >> 5, cp = (i & 31) * 2;
        float f0 = ss[n * 66 + cp], f1 = ss[n * 66 + cp + 1];
        int ch = cp >> 3;
        unsigned off = (unsigned)(n * 128 + ((ch ^ (n & 7)) << 4) + (cp & 7) * 2);
        __nv_bfloat16 h0 = __float2bfloat16(f0), h1 = __float2bfloat16(f1);
        *(unsigned*)(smem + SH + off) = pkbf(f0, f1);
        *(unsigned*)(smem + SL + off) =
            pkbf(f0 - __bfloat162float(h0), f1 - __bfloat162float(h1));
    }
    if (tid < 64) {
        float s = 0.f;
#pragma unroll 16
        for (int c = 0; c < 64; c++) { float v = ss[tid * 66 + c]; s += v * v; }
        sn[tid] = s;
    }
    __syncthreads();

    int ri = lane & 7, mat = lane >> 3;
    float acc[2][8][4];
#pragma unroll
    for (int i = 0; i < 2; i++)
#pragma unroll
        for (int j = 0; j < 8; j++)
#pragma unroll
            for (int q = 0; q < 4; q++) acc[i][j][q] = 0.f;

    {
        int w = wid;
        int arow = (lane >> 2), acol = (lane & 3) * 2;
#pragma unroll
        for (int k16 = 0; k16 < 4; k16++) {
#pragma unroll
            for (int half = 0; half < 2; half++) {
                unsigned bh[4][2], bl[4][2];
                int chb = k16 * 2 + (mat & 1);
#pragma unroll
                for (int ng = 0; ng < 2; ng++) {
                    int row = half * 32 + ng * 16 + ri + ((mat >> 1) << 3);
                    unsigned sw = (unsigned)(row * 128 + ((chb ^ (row & 7)) << 4));
                    unsigned r0, r1, r2, r3;
                    ldsm4(r0, r1, r2, r3, sb + SH + sw);
                    bh[2 * ng][0] = r0; bh[2 * ng][1] = r1;
                    bh[2 * ng + 1][0] = r2; bh[2 * ng + 1][1] = r3;
                    ldsm4(r0, r1, r2, r3, sb + SL + sw);
                    bl[2 * ng][0] = r0; bl[2 * ng][1] = r1;
                    bl[2 * ng + 1][0] = r2; bl[2 * ng + 1][1] = r3;
                }
#pragma unroll
                for (int mi = 0; mi < 2; mi++) {
                    long wbase = (long)(w * 32 + mi * 16 + arow) * 64 + k16 * 16 + acol;
                    unsigned ah[4];
                    ah[0] = *(const unsigned*)(g_w2bh + wbase);
                    ah[1] = *(const unsigned*)(g_w2bh + wbase + 8 * 64);
                    ah[2] = *(const unsigned*)(g_w2bh + wbase + 8);
                    ah[3] = *(const unsigned*)(g_w2bh + wbase + 8 * 64 + 8);
#pragma unroll
                    for (int nj = 0; nj < 4; nj++) {
                        mma16816(acc[mi][half * 4 + nj], ah, bh[nj]);
                        mma16816(acc[mi][half * 4 + nj], ah, bl[nj]);
                    }
                    ah[0] = *(const unsigned*)(g_w2bl + wbase);
                    ah[1] = *(const unsigned*)(g_w2bl + wbase + 8 * 64);
                    ah[2] = *(const unsigned*)(g_w2bl + wbase + 8);
                    ah[3] = *(const unsigned*)(g_w2bl + wbase + 8 * 64 + 8);
#pragma unroll
                    for (int nj = 0; nj < 4; nj++)
                        mma16816(acc[mi][half * 4 + nj], ah, bh[nj]);
                }
            }
        }
    }
    __syncthreads();

    {
        int w = wid;
#pragma unroll
        for (int mi = 0; mi < 2; mi++) {
            int oc0 = mi * 16 + (lane >> 2);
#pragma unroll
            for (int nj = 0; nj < 8; nj++) {
                int n0 = nj * 8 + (lane & 3) * 2;
#pragma unroll
                for (int q = 0; q < 4; q++) {
                    int oc = (q < 2) ? oc0 : oc0 + 8;
                    int n = n0 + (q & 1);
                    Mt[(w * 64 + n) * 36 + oc] = acc[mi][nj][q];
                }
            }
        }
    }
    __syncthreads();

    if (tid < 256) {
        int t = tid;
        ull xr2[32]; float xn = 0.f;
#pragma unroll
        for (int c2 = 0; c2 < 32; c2++) {
            float f0 = g_out1[(b * 64 + 2 * c2) * 256 + t];
            float f1 = g_out1[(b * 64 + 2 * c2 + 1) * 256 + t];
            xn += f0 * f0 + f1 * f1;
            xr2[c2] = pack2(f0, f1);
        }

        float bd[9]; int bi[9];
#pragma unroll
        for (int k = 0; k < 9; k++) { bd[k] = 3.0e38f; bi[k] = 0; }
        for (int n = 0; n < 64; n++) {
            const ull* sp = (const ull*)&ss[n * 66];
            ull d2 = 0ull;
#pragma unroll
            for (int j = 0; j < 32; j++) fma2(d2, xr2[j], sp[j]);
            float2 dv = unpk(d2);
            float d = xn + sn[n] - 2.f * (dv.x + dv.y);
            if (d < bd[8]) {
                bool placed = false;
#pragma unroll
                for (int j = 8; j > 0; --j) {
                    if (!placed) {
                        if (d < bd[j - 1]) { bd[j] = bd[j - 1]; bi[j] = bi[j - 1]; }
                        else { bd[j] = d; bi[j] = n; placed = true; }
                    }
                }
                if (!placed) { bd[0] = d; bi[0] = n; }
            }
        }

#pragma unroll
        for (int half = 0; half < 2; half++) {
            float acm[16];
#pragma unroll
            for (int o = 0; o < 16; o++) acm[o] = bb[half * 16 + o];
#pragma unroll
            for (int k = 0; k < 9; k++) {
                const float4* m4 = (const float4*)&Mt[(k * 64 + bi[k]) * 36 + half * 16];
                float4 v0 = m4[0], v1 = m4[1], v2 = m4[2], v3 = m4[3];
                acm[0] += v0.x; acm[1] += v0.y; acm[2] += v0.z; acm[3] += v0.w;
                acm[4] += v1.x; acm[5] += v1.y; acm[6] += v1.z; acm[7] += v1.w;
                acm[8] += v2.x; acm[9] += v2.y; acm[10] += v2.z; acm[11] += v2.w;
                acm[12] += v3.x; acm[13] += v3.y; acm[14] += v3.z; acm[15] += v3.w;
            }
#pragma unroll
            for (int j = 0; j < 8; j++)
                c2_store((long)b * 16384 + t * 64 + 32 + half * 16 + 2 * j,
                         fmaxf(acm[2 * j], 0.f), fmaxf(acm[2 * j + 1], 0.f));
        }
    }
}

// ======== Layer 2 pw as bf16 split mma: C[128][256] = W[128x64] * cat2 ==========
__global__ __launch_bounds__(256) void k_l2_pw(const float* __restrict__ bp) {
    extern __shared__ __align__(16) char smem[];
    unsigned sb = smem_u32(smem);
    int b = blockIdx.x, tid = threadIdx.x, lane = tid & 31, warp = tid >> 5;

#pragma unroll
    for (int j = 0; j < 8; j++) {
        int q = tid + j * 256;
        int row = q >> 3, ch = q & 7;
        unsigned dst = sb + row * 128 + ((ch ^ (row & 7)) << 4);
        cpa16(dst, g_c2h + (long)b * 16384 + row * 64 + ch * 8);
        cpa16(dst + 32768, g_c2l + (long)b * 16384 + row * 64 + ch * 8);
    }
#pragma unroll
    for (int j = 0; j < 4; j++) {
        int q = tid + j * 256;
        int row = q >> 3, ch = q & 7;
        unsigned dst = sb + 65536 + row * 128 + ((ch ^ (row & 7)) << 4);
        cpa16(dst, g_wph + row * 64 + ch * 8);
        cpa16(dst + 16384, g_wpl + row * 64 + ch * 8);
    }
    cpa_commit();
    cpa_wait0();
    __syncthreads();

    int m_base = (warp & 1) * 64;
    int n_base = (warp >> 1) * 64;
    int ri = lane & 7, mat = lane >> 3;

    float acc[4][8][4];
#pragma unroll
    for (int i = 0; i < 4; i++)
#pragma unroll
        for (int j = 0; j < 8; j++)
#pragma unroll
            for (int q = 0; q < 4; q++) acc[i][j][q] = 0.f;

#pragma unroll
    for (int kk = 0; kk < 4; kk++) {
        unsigned af[4][4], bh[8][2], bl[8][2];
#pragma unroll
        for (int ng = 0; ng < 4; ng++) {
            int row = n_base + ng * 16 + ri + ((mat >> 1) << 3);
            int ch = kk * 2 + (mat & 1);
            unsigned bd_ = sb + row * 128 + ((ch ^ (row & 7)) << 4);
            unsigned r0, r1, r2, r3;
            ldsm4(r0, r1, r2, r3, bd_);
            bh[2 * ng][0] = r0; bh[2 * ng][1] = r1;
            bh[2 * ng + 1][0] = r2; bh[2 * ng + 1][1] = r3;
            ldsm4(r0, r1, r2, r3, bd_ + 32768);
            bl[2 * ng][0] = r0; bl[2 * ng][1] = r1;
            bl[2 * ng + 1][0] = r2; bl[2 * ng + 1][1] = r3;
        }
#pragma unroll
        for (int mi = 0; mi < 4; mi++) {
            int row = m_base + mi * 16 + ri + ((mat & 1) << 3);
            int ch = kk * 2 + (mat >> 1);
            unsigned ad = sb + 65536 + row * 128 + ((ch ^ (row & 7)) << 4);
            ldsm4(af[mi][0], af[mi][1], af[mi][2], af[mi][3], ad);
        }
#pragma unroll
        for (int mi = 0; mi < 4; mi++)
#pragma unroll
            for (int ni = 0; ni < 8; ni++) {
                mma16816(acc[mi][ni], af[mi], bh[ni]);
                mma16816(acc[mi][ni], af[mi], bl[ni]);
            }
#pragma unroll
        for (int mi = 0; mi < 4; mi++) {
            int row = m_base + mi * 16 + ri + ((mat & 1) << 3);
            int ch = kk * 2 + (mat >> 1);
            unsigned ad = sb + 81920 + row * 128 + ((ch ^ (row & 7)) << 4);
            ldsm4(af[mi][0], af[mi][1], af[mi][2], af[mi][3], ad);
        }
#pragma unroll
        for (int mi = 0; mi < 4; mi++)
#pragma unroll
            for (int ni = 0; ni < 8; ni++)
                mma16816(acc[mi][ni], af[mi], bh[ni]);
    }

#pragma unroll
    for (int mi = 0; mi < 4; mi++) {
        int oc0 = m_base + mi * 16 + (lane >> 2);
        float bias0 = bp[oc0], bias1 = bp[oc0 + 8];
#pragma unroll
        for (int ni = 0; ni < 8; ni++) {
            int t0 = n_base + ni * 8 + (lane & 3) * 2;
#pragma unroll
            for (int q = 0; q < 4; q++) {
                int oc = (q < 2) ? oc0 : oc0 + 8;
                float v = acc[mi][ni][q] + ((q < 2) ? bias0 : bias1);
                int t = t0 + (q & 1);
                int cp = oc >> 2, ii = (oc >> 1) & 1, jj = oc & 1;
                int h = t >> 4, w = t & 15;
                long pos = (long)b * 32768 + cp * 1024 + (2 * h + ii) * 32 + 2 * w + jj;
                __nv_bfloat16 hi = __float2bfloat16(v);
                g_ahi[pos] = hi;
                g_alo[pos] = __float2bfloat16(v - __bfloat162float(hi));
            }
        }
    }
}

// ======================= fc1: bf16 split GEMM, 3-stage pipeline =================
__global__ __launch_bounds__(512) void k_fc1t(const float* __restrict__ W) {
    extern __shared__ __align__(16) char smem[];
    unsigned sbase = smem_u32(smem);
    int tid = threadIdx.x, lane = tid & 31, warp = tid >> 5;
    int n0 = blockIdx.x * 128, sk = blockIdx.z;
    long kbase = (long)sk * 2048;

    int m_base = (warp & 3) * 64;
    int n_base = (warp >> 2) * 32;

    int aq[2], ac[2];
#pragma unroll
    for (int j = 0; j < 2; j++) { int q = tid + j * 512; aq[j] = q >> 2; ac[j] = q & 3; }
    int wr = tid >> 2, wc = tid & 3;

    float acc[4][4][4];
#pragma unroll
    for (int i = 0; i < 4; i++)
#pragma unroll
        for (int j = 0; j < 4; j++)
#pragma unroll
            for (int q = 0; q < 4; q++) acc[i][j][q] = 0.f;

    const float* wgp = W + (long)(n0 + wr) * 32768 + kbase + wc * 8;

    float4 wa0 = *(const float4*)(wgp), wb0 = *(const float4*)(wgp + 4);
    float4 wa1 = *(const float4*)(wgp + 32), wb1 = *(const float4*)(wgp + 36);
#pragma unroll
    for (int j = 0; j < 2; j++) {
        int r = aq[j], c = ac[j];
        unsigned sw = (unsigned)(r * 64 + ((c ^ ((r >> 1) & 3)) << 4));
        cpa16(sbase + sw, g_ahi + (long)r * 32768 + kbase + c * 8);
        cpa16(sbase + 16384 + sw, g_alo + (long)r * 32768 + kbase + c * 8);
    }
    cpa_commit();
#pragma unroll
    for (int j = 0; j < 2; j++) {
        int r = aq[j], c = ac[j];
        unsigned sw = (unsigned)(r * 64 + ((c ^ ((r >> 1) & 3)) << 4));
        cpa16(sbase + 49152 + sw, g_ahi + (long)r * 32768 + kbase + 32 + c * 8);
        cpa16(sbase + 49152 + 16384 + sw, g_alo + (long)r * 32768 + kbase + 32 + c * 8);
    }
    cpa_commit();
    wsplit_store(sbase + 32768, wr, wc, wa0, wb0);
    wsplit_store(sbase + 49152 + 32768, wr, wc, wa1, wb1);

    int ri = lane & 7, mat = lane >> 3;

    for (int it = 0; it < 64; it++) {
        unsigned stb = sbase + (unsigned)(it % 3) * 49152u;
        cpa_wait1();
        __syncthreads();

        float4 wna, wnb;
        unsigned nb = sbase + (unsigned)((it + 2) % 3) * 49152u;
        if (it < 62) {
            long ko = kbase + (it + 2) * 32;
            wna = *(const float4*)(wgp + (it + 2) * 32);
            wnb = *(const float4*)(wgp + (it + 2) * 32 + 4);
#pragma unroll
            for (int j = 0; j < 2; j++) {
                int r = aq[j], c = ac[j];
                unsigned sw = (unsigned)(r * 64 + ((c ^ ((r >> 1) & 3)) << 4));
                cpa16(nb + sw, g_ahi + (long)r * 32768 + ko + c * 8);
                cpa16(nb + 16384 + sw, g_alo + (long)r * 32768 + ko + c * 8);
            }
        }
        cpa_commit();

#pragma unroll
        for (int k16 = 0; k16 < 2; k16++) {
            unsigned af[4][4], bh[4][2], bl[4][2];
#pragma unroll
            for (int ng = 0; ng < 2; ng++) {
                int row = n_base + ng * 16 + ri + ((mat >> 1) << 3);
                int c = k16 * 2 + (mat & 1);
                unsigned bd_ = stb + 32768 + row * 64 + ((c ^ ((row >> 1) & 3)) << 4);
                unsigned r0, r1, r2, r3;
                ldsm4(r0, r1, r2, r3, bd_);
                bh[2 * ng][0] = r0; bh[2 * ng][1] = r1;
                bh[2 * ng + 1][0] = r2; bh[2 * ng + 1][1] = r3;
                ldsm4(r0, r1, r2, r3, bd_ + 8192);
                bl[2 * ng][0] = r0; bl[2 * ng][1] = r1;
                bl[2 * ng + 1][0] = r2; bl[2 * ng + 1][1] = r3;
            }
#pragma unroll
            for (int mi = 0; mi < 4; mi++) {
                int row = m_base + mi * 16 + ri + ((mat & 1) << 3);
                int c = k16 * 2 + (mat >> 1);
                unsigned ad = stb + row * 64 + ((c ^ ((row >> 1) & 3)) << 4);
                ldsm4(af[mi][0], af[mi][1], af[mi][2], af[mi][3], ad);
            }
#pragma unroll
            for (int mi = 0; mi < 4; mi++)
#pragma unroll
                for (int ni = 0; ni < 4; ni++) {
                    mma16816(acc[mi][ni], af[mi], bh[ni]);
                    mma16816(acc[mi][ni], af[mi], bl[ni]);
                }
#pragma unroll
            for (int mi = 0; mi < 4; mi++) {
                int row = m_base + mi * 16 + ri + ((mat & 1) << 3);
                int c = k16 * 2 + (mat >> 1);
                unsigned ad = stb + 16384 + row * 64 + ((c ^ ((row >> 1) & 3)) << 4);
                ldsm4(af[mi][0], af[mi][1], af[mi][2], af[mi][3], ad);
            }
#pragma unroll
            for (int mi = 0; mi < 4; mi++)
#pragma unroll
                for (int ni = 0; ni < 4; ni++)
                    mma16816(acc[mi][ni], af[mi], bh[ni]);
        }

        if (it < 62)
            wsplit_store(nb + 32768, wr, wc, wna, wnb);
    }

    float* slab = g_fc1p + (long)sk * BATCH * 1024;
#pragma unroll
    for (int mi = 0; mi < 4; mi++)
#pragma unroll
        for (int ni = 0; ni < 4; ni++) {
            int m = m_base + mi * 16 + (lane >> 2);
            int n = n0 + n_base + ni * 8 + (lane & 3) * 2;
            *(float2*)&slab[(long)m * 1024 + n] =
                make_float2(acc[mi][ni][0], acc[mi][ni][1]);
            *(float2*)&slab[(long)(m + 8) * 1024 + n] =
                make_float2(acc[mi][ni][2], acc[mi][ni][3]);
        }
}

// ======================= fc2 (fused slab-reduce + relu + fc2) ===================
__global__ __launch_bounds__(256) void k_fc2(const float* __restrict__ fc1b,
                                             const float* __restrict__ w2,
                                             const float* __restrict__ b2,
                                             float* __restrict__ out) {
    __shared__ __align__(16) float hs[1024];
    __shared__ float red[10 * 256];
    int b = blockIdx.x, tid = threadIdx.x;
    for (int j = tid; j < 1024; j += 256) {
        float s = 0.f;
#pragma unroll
        for (int q = 0; q < 16; q++) s += g_fc1p[(long)q * BATCH * 1024 + b * 1024 + j];
        hs[j] = fmaxf(s + fc1b[j], 0.f);
    }
    __syncthreads();
    float p[10];
#pragma unroll
    for (int n = 0; n < 10; n++) p[n] = 0.f;
    for (int j = tid; j < 1024; j += 256) {
        float hv = hs[j];
#pragma unroll
        for (int n = 0; n < 10; n++) p[n] += hv * w2[n * 1024 + j];
    }
#pragma unroll
    for (int n = 0; n < 10; n++) red[n * 256 + tid] = p[n];
    __syncthreads();
    for (int s = 128; s > 0; s >>= 1) {
        if (tid < s) {
#pragma unroll
            for (int n = 0; n < 10; n++) red[n * 256 + tid] += red[n * 256 + tid + s];
        }
        __syncthreads();
    }
    if (tid < 10) out[b * 10 + tid] = red[tid * 256] + b2[tid];
}

// =================================================================================
extern "C" void kernel_launch(void* const* d_in, const int* in_sizes, int n_in,
                              void* d_out, int out_size) {
    const float* x    = (const float*)d_in[0];
    const int*   idx1 = (const int*)d_in[1];
    const int*   idx2 = (const int*)d_in[2];
    const float* w1a  = (const float*)d_in[3];
    const float* b1a  = (const float*)d_in[4];
    const float* w1b  = (const float*)d_in[5];
    const float* b1b  = (const float*)d_in[6];
    const float* w1p  = (const float*)d_in[7];
    const float* b1p  = (const float*)d_in[8];
    const float* w2a  = (const float*)d_in[9];
    const float* b2a  = (const float*)d_in[10];
    const float* w2b  = (const float*)d_in[11];
    const float* b2b  = (const float*)d_in[12];
    const float* w2p  = (const float*)d_in[13];
    const float* b2p  = (const float*)d_in[14];
    const float* fc1w = (const float*)d_in[15];
    const float* fc1b = (const float*)d_in[16];
    const float* fc2w = (const float*)d_in[17];
    const float* fc2b = (const float*)d_in[18];
    float* out = (float*)d_out;

    const int smem_l2c  = 139776;
    const int smem_knn  = 100096;
    const int smem_pw   = 98304;
    const int smem_fc1t = 147456;
    cudaFuncSetAttribute(k_l2c,    cudaFuncAttributeMaxDynamicSharedMemorySize, smem_l2c);
    cudaFuncSetAttribute(k_l2_knn, cudaFuncAttributeMaxDynamicSharedMemorySize, smem_knn);
    cudaFuncSetAttribute(k_l2_pw,  cudaFuncAttributeMaxDynamicSharedMemorySize, smem_pw);
    cudaFuncSetAttribute(k_fc1t,   cudaFuncAttributeMaxDynamicSharedMemorySize, smem_fc1t);

    k_repack<<<72, 256>>>(w1a, w1b, w2a, w2b, w2p);
    k_l1<<<dim3(BATCH, 2), 128>>>(x, idx1, b1a, b1b, w1p, b1p);
    k_l2_knn<<<BATCH, 288, smem_knn>>>(idx2, b2b);
    k_l2c<<<BATCH / 2, 256, smem_l2c>>>(b2a);
    k_l2_pw<<<BATCH, 256, smem_pw>>>(b2p);
    k_fc1t<<<dim3(8, 1, 16), 512, smem_fc1t>>>(fc1w);
    k_fc2<<<BATCH, 256>>>(fc1b, fc2w, fc2b, out);
}

// round 17
// speedup vs baseline: 1.0961x; 1.0014x over previous
#include <cuda_runtime.h>
#include <cuda_bf16.h>

typedef unsigned long long ull;
constexpr int BATCH = 256;

// ---------------- scratch (device globals) ----------------
__device__ __align__(16) float g_out1[BATCH * 64 * 256];
__device__ __align__(16) float g_fc1p[16 * BATCH * 1024];
__device__ __align__(16) float g_r1a[1728];
__device__ __align__(16) float g_r1b[1728];
__device__ __align__(16) __nv_bfloat16 g_o1h[BATCH * 16384];  // out1 hi [t][c]
__device__ __align__(16) __nv_bfloat16 g_o1l[BATCH * 16384];
__device__ __align__(16) __nv_bfloat16 g_w2ah[9 * 32 * 64];   // conv W [tap][oc][c]
__device__ __align__(16) __nv_bfloat16 g_w2al[9 * 32 * 64];
__device__ __align__(16) __nv_bfloat16 g_w2bh[9 * 32 * 64];   // knn W [tap][oc][c]
__device__ __align__(16) __nv_bfloat16 g_w2bl[9 * 32 * 64];
__device__ __align__(16) __nv_bfloat16 g_c2h[BATCH * 16384];  // cat2 hi [t][c]
__device__ __align__(16) __nv_bfloat16 g_c2l[BATCH * 16384];
__device__ __align__(16) __nv_bfloat16 g_wph[8192];           // w2p hi [oc][c]
__device__ __align__(16) __nv_bfloat16 g_wpl[8192];
__device__ __align__(16) __nv_bfloat16 g_ahi[BATCH * 32768];
__device__ __align__(16) __nv_bfloat16 g_alo[BATCH * 32768];

// ---------------- f32x2 helpers ----------------
__device__ __forceinline__ ull pack2(float lo, float hi) {
    ull r;
    asm("mov.b64 %0, {%1, %2};" : "=l"(r) : "r"(__float_as_uint(lo)), "r"(__float_as_uint(hi)));
    return r;
}
__device__ __forceinline__ ull packd(float s) { return pack2(s, s); }
__device__ __forceinline__ void fma2(ull& d, ull a, ull b) {
    asm("fma.rn.f32x2 %0, %1, %2, %3;" : "=l"(d) : "l"(a), "l"(b), "l"(d));
}
__device__ __forceinline__ float2 unpk(ull v) {
    unsigned lo, hi;
    asm("mov.b64 {%0, %1}, %2;" : "=r"(lo), "=r"(hi) : "l"(v));
    float2 f; f.x = __uint_as_float(lo); f.y = __uint_as_float(hi);
    return f;
}

// ---------------- mma.sync helpers ----------------
__device__ __forceinline__ unsigned smem_u32(const void* p) {
    unsigned a;
    asm("{ .reg .u64 t; cvta.to.shared.u64 t, %1; cvt.u32.u64 %0, t; }" : "=r"(a) : "l"(p));
    return a;
}
__device__ __forceinline__ void ldsm4(unsigned& r0, unsigned& r1, unsigned& r2, unsigned& r3,
                                      unsigned addr) {
    asm volatile("ldmatrix.sync.aligned.m8n8.x4.shared.b16 {%0,%1,%2,%3}, [%4];"
                 : "=r"(r0), "=r"(r1), "=r"(r2), "=r"(r3) : "r"(addr));
}
__device__ __forceinline__ void mma16816(float* c, const unsigned* a, const unsigned* b) {
    asm volatile(
        "mma.sync.aligned.m16n8k16.row.col.f32.bf16.bf16.f32 "
        "{%0,%1,%2,%3},{%4,%5,%6,%7},{%8,%9},{%0,%1,%2,%3};"
        : "+f"(c[0]), "+f"(c[1]), "+f"(c[2]), "+f"(c[3])
        : "r"(a[0]), "r"(a[1]), "r"(a[2]), "r"(a[3]), "r"(b[0]), "r"(b[1]));
}
__device__ __forceinline__ void cpa16(unsigned dst, const void* src) {
    asm volatile("cp.async.cg.shared.global [%0], [%1], 16;" :: "r"(dst), "l"(src));
}
__device__ __forceinline__ void cpa_commit() { asm volatile("cp.async.commit_group;"); }
__device__ __forceinline__ void cpa_wait0() {
    asm volatile("cp.async.wait_group 0;" ::: "memory");
}
__device__ __forceinline__ void cpa_wait1() {
    asm volatile("cp.async.wait_group 1;" ::: "memory");
}
__device__ __forceinline__ void sts128(unsigned addr, uint4 v) {
    asm volatile("st.shared.v4.b32 [%0], {%1,%2,%3,%4};"
                 :: "r"(addr), "r"(v.x), "r"(v.y), "r"(v.z), "r"(v.w));
}
__device__ __forceinline__ unsigned pkbf(float a, float b) {
    __nv_bfloat16 ha = __float2bfloat16(a), hb = __float2bfloat16(b);
    return ((unsigned)__bfloat16_as_ushort(hb) << 16) | __bfloat16_as_ushort(ha);
}
__device__ __forceinline__ void wsplit_store(unsigned hi_base, int row, int c,
                                             float4 a, float4 b) {
    unsigned sw = (unsigned)(row * 64 + ((c ^ ((row >> 1) & 3)) << 4));
    uint4 hi, lo;
    hi.x = pkbf(a.x, a.y); hi.y = pkbf(a.z, a.w);
    hi.z = pkbf(b.x, b.y); hi.w = pkbf(b.z, b.w);
    __nv_bfloat16 t0 = __float2bfloat16(a.x), t1 = __float2bfloat16(a.y);
    __nv_bfloat16 t2 = __float2bfloat16(a.z), t3 = __float2bfloat16(a.w);
    __nv_bfloat16 t4 = __float2bfloat16(b.x), t5 = __float2bfloat16(b.y);
    __nv_bfloat16 t6 = __float2bfloat16(b.z), t7 = __float2bfloat16(b.w);
    lo.x = pkbf(a.x - __bfloat162float(t0), a.y - __bfloat162float(t1));
    lo.y = pkbf(a.z - __bfloat162float(t2), a.w - __bfloat162float(t3));
    lo.z = pkbf(b.x - __bfloat162float(t4), b.y - __bfloat162float(t5));
    lo.w = pkbf(b.z - __bfloat162float(t6), b.w - __bfloat162float(t7));
    sts128(hi_base + sw, hi);
    sts128(hi_base + 8192 + sw, lo);
}
__device__ __forceinline__ void c2_store(long base, float r0, float r1) {
    __nv_bfloat16 h0 = __float2bfloat16(r0), h1 = __float2bfloat16(r1);
    *(unsigned*)&g_c2h[base] = pkbf(r0, r1);
    *(unsigned*)&g_c2l[base] = pkbf(r0 - __bfloat162float(h0), r1 - __bfloat162float(h1));
}

// ---------------- weight repack ----------------
__global__ __launch_bounds__(256) void k_repack(const float* __restrict__ w1a,
                                                const float* __restrict__ w1b,
                                                const float* __restrict__ w2a,
                                                const float* __restrict__ w2b,
                                                const float* __restrict__ w2p) {
    int i = blockIdx.x * 256 + threadIdx.x;
    if (i < 1728) {
        int oc = i / 108, rest = i % 108;
        g_r1a[rest * 16 + oc] = w1a[i];
        g_r1b[rest * 16 + oc] = w1b[i];
    }
    if (i < 8192) {
        float v = w2p[i];
        __nv_bfloat16 h = __float2bfloat16(v);
        g_wph[i] = h;
        g_wpl[i] = __float2bfloat16(v - __bfloat162float(h));
    }
    if (i < 18432) {
        int oc = i / 576, rest = i % 576;
        int c = rest / 9, k = rest % 9;
        float va = w2a[i];
        __nv_bfloat16 ha = __float2bfloat16(va);
        g_w2ah[(k * 32 + oc) * 64 + c] = ha;
        g_w2al[(k * 32 + oc) * 64 + c] = __float2bfloat16(va - __bfloat162float(ha));
        float vb = w2b[i];
        __nv_bfloat16 hb = __float2bfloat16(vb);
        g_w2bh[(k * 32 + oc) * 64 + c] = hb;
        g_w2bl[(k * 32 + oc) * 64 + c] = __float2bfloat16(vb - __bfloat162float(hb));
    }
}

// ======================= Layer 1 FUSED, pixel-split x2 ==========================
__global__ __launch_bounds__(128) void k_l1(const float* __restrict__ x,
                                            const int* __restrict__ idx,
                                            const float* __restrict__ b1a,
                                            const float* __restrict__ b1b,
                                            const float* __restrict__ wp,
                                            const float* __restrict__ bp) {
    __shared__ __align__(16) float xs[12 * 256];
    __shared__ __align__(16) float ss[12 * 64];
    __shared__ float sn[64];
    __shared__ __align__(16) float wsa[1728];
    __shared__ __align__(16) float wsb[1728];
    __shared__ __align__(16) float wsp[64 * 32];
    int b = blockIdx.x, tid = threadIdx.x;
    int p = blockIdx.y * 128 + tid;

    for (int i = tid; i < 12 * 256; i += 128) {
        int cu = i >> 8, t = i & 255;
        int h = t >> 4, w = t & 15;
        int c = cu >> 2, ii = (cu >> 1) & 1, jj = cu & 1;
        xs[i] = x[((b * 3 + c) * 32 + (2 * h + ii)) * 32 + 2 * w + jj];
    }
    for (int i = tid; i < 1728; i += 128) { wsa[i] = g_r1a[i]; wsb[i] = g_r1b[i]; }
    for (int i = tid; i < 64 * 32; i += 128) wsp[i] = wp[i];
    __syncthreads();
    for (int i = tid; i < 12 * 64; i += 128)
        ss[i] = xs[(i >> 6) * 256 + idx[i & 63]];
    __syncthreads();
    if (tid < 64) {
        float s = 0.f;
#pragma unroll
        for (int c = 0; c < 12; c++) { float v = ss[c * 64 + tid]; s += v * v; }
        sn[tid] = s;
    }
    __syncthreads();

    int h = p >> 4, w = p & 15;

    ull acv[8];
#pragma unroll
    for (int o = 0; o < 8; o++) acv[o] = pack2(b1a[2 * o], b1a[2 * o + 1]);
    for (int c = 0; c < 12; c++) {
        float pp[9];
#pragma unroll
        for (int dy = 0; dy < 3; dy++)
#pragma unroll
            for (int dx = 0; dx < 3; dx++) {
                int y = h + dy - 1, xq = w + dx - 1;
                pp[dy * 3 + dx] = (y >= 0 && y < 16 && xq >= 0 && xq < 16)
                                      ? xs[c * 256 + y * 16 + xq] : 0.f;
            }
#pragma unroll
        for (int tap = 0; tap < 9; tap++) {
            ull s2 = packd(pp[tap]);
            const longlong2* wv = (const longlong2*)&wsa[(c * 9 + tap) * 16];
#pragma unroll
            for (int q = 0; q < 4; q++) {
                longlong2 w4 = wv[q];
                fma2(acv[q * 2 + 0], s2, (ull)w4.x);
                fma2(acv[q * 2 + 1], s2, (ull)w4.y);
            }
        }
    }

    float xr[12]; float xn = 0.f;
#pragma unroll
    for (int c = 0; c < 12; c++) { float v = xs[c * 256 + p]; xr[c] = v; xn += v * v; }

    float bd[9]; int bi[9];
#pragma unroll
    for (int k = 0; k < 9; k++) { bd[k] = 3.0e38f; bi[k] = 0; }
    for (int n = 0; n < 64; n++) {
        float dot = 0.f;
#pragma unroll
        for (int c = 0; c < 12; c++) dot += xr[c] * ss[c * 64 + n];
        float d = xn + sn[n] - 2.f * dot;
        if (d < bd[8]) {
            bool placed = false;
#pragma unroll
            for (int j = 8; j > 0; --j) {
                if (!placed) {
                    if (d < bd[j - 1]) { bd[j] = bd[j - 1]; bi[j] = bi[j - 1]; }
                    else { bd[j] = d; bi[j] = n; placed = true; }
                }
            }
            if (!placed) { bd[0] = d; bi[0] = n; }
        }
    }

    ull akn[8];
#pragma unroll
    for (int o = 0; o < 8; o++) akn[o] = pack2(b1b[2 * o], b1b[2 * o + 1]);
#pragma unroll
    for (int c = 0; c < 12; c++) {
#pragma unroll
        for (int k = 0; k < 9; k++) {
            ull s2 = packd(ss[c * 64 + bi[k]]);
            const longlong2* wv = (const longlong2*)&wsb[(c * 9 + k) * 16];
#pragma unroll
            for (int q = 0; q < 4; q++) {
                longlong2 w4 = wv[q];
                fma2(akn[q * 2 + 0], s2, (ull)w4.x);
                fma2(akn[q * 2 + 1], s2, (ull)w4.y);
            }
        }
    }

    ull xv[16];
#pragma unroll
    for (int o = 0; o < 8; o++) {
        float2 v = unpk(acv[o]);
        xv[o] = pack2(fmaxf(v.x, 0.f), fmaxf(v.y, 0.f));
        float2 u = unpk(akn[o]);
        xv[8 + o] = pack2(fmaxf(u.x, 0.f), fmaxf(u.y, 0.f));
    }
    float vb[8];
    for (int oc = 0; oc < 64; oc++) {
        ull a2 = 0ull;
        const longlong2* wv = (const longlong2*)&wsp[oc * 32];
#pragma unroll
        for (int q = 0; q < 8; q++) {
            longlong2 w4 = wv[q];
            fma2(a2, xv[q * 2 + 0], (ull)w4.x);
            fma2(a2, xv[q * 2 + 1], (ull)w4.y);
        }
        float2 v = unpk(a2);
        float val = v.x + v.y + bp[oc];
        g_out1[(b * 64 + oc) * 256 + p] = val;
        vb[oc & 7] = val;
        if ((oc & 7) == 7) {
            uint4 hi, lo;
            hi.x = pkbf(vb[0], vb[1]); hi.y = pkbf(vb[2], vb[3]);
            hi.z = pkbf(vb[4], vb[5]); hi.w = pkbf(vb[6], vb[7]);
            float l[8];
#pragma unroll
            for (int j = 0; j < 8; j++)
                l[j] = vb[j] - __bfloat162float(__float2bfloat16(vb[j]));
            lo.x = pkbf(l[0], l[1]); lo.y = pkbf(l[2], l[3]);
            lo.z = pkbf(l[4], l[5]); lo.w = pkbf(l[6], l[7]);
            long base = (long)b * 16384 + p * 64 + (oc - 7);
            *(uint4*)&g_o1h[base] = hi;
            *(uint4*)&g_o1l[base] = lo;
        }
    }
}

// ========== Layer 2 conv 3x3: implicit-GEMM mma, persistent over 2 images =======
__global__ __launch_bounds__(256) void k_l2c(const float* __restrict__ ba) {
    extern __shared__ __align__(16) char smem[];
    unsigned sb = smem_u32(smem);
    const unsigned XH = 0, XL = 33024, AH = 66048, AL = 102912;
    int tid = threadIdx.x, lane = tid & 31, warp = tid >> 5;

    if (tid < 16) {
        uint4 z = make_uint4(0, 0, 0, 0);
        unsigned pl = (tid >> 3) ? XL : XH;
        sts128(sb + pl + 256 * 128 + ((tid & 7) << 4), z);
    }
#pragma unroll
    for (int j = 0; j < 9; j++) {
        int q = tid + j * 256;
        int row = q >> 3, ch = q & 7;
        unsigned sw = (unsigned)(row * 128 + ((ch ^ (row & 7)) << 4));
        cpa16(sb + AH + sw, g_w2ah + row * 64 + ch * 8);
        cpa16(sb + AL + sw, g_w2al + row * 64 + ch * 8);
    }
    cpa_commit();

    int n_base = warp * 32;
    int ri = lane & 7, mat = lane >> 3;

    for (int img = 0; img < 2; img++) {
        int b = blockIdx.x * 2 + img;
        __syncthreads();
#pragma unroll
        for (int j = 0; j < 8; j++) {
            int q = tid + j * 256;
            int row = q >> 3, ch = q & 7;
            unsigned sw = (unsigned)(row * 128 + ((ch ^ (row & 7)) << 4));
            cpa16(sb + XH + sw, g_o1h + (long)b * 16384 + row * 64 + ch * 8);
            cpa16(sb + XL + sw, g_o1l + (long)b * 16384 + row * 64 + ch * 8);
        }
        cpa_commit();
        cpa_wait0();
        __syncthreads();

        float acc[2][4][4];
#pragma unroll
        for (int i = 0; i < 2; i++)
#pragma unroll
            for (int j = 0; j < 4; j++)
#pragma unroll
                for (int q = 0; q < 4; q++) acc[i][j][q] = 0.f;

#pragma unroll
        for (int tap = 0; tap < 9; tap++) {
            int dy = tap / 3, dx = tap % 3;
            int rin[2];
#pragma unroll
            for (int ng = 0; ng < 2; ng++) {
                int t = n_base + ng * 16 + ri + ((mat >> 1) << 3);
                int h = (t >> 4) + dy - 1, w = (t & 15) + dx - 1;
                rin[ng] = ((unsigned)h < 16u && (unsigned)w < 16u) ? h * 16 + w : 256;
            }
#pragma unroll
            for (int k16 = 0; k16 < 4; k16++) {
                unsigned af[2][4], bh[4][2], bl[4][2];
                int chb = k16 * 2 + (mat & 1);
#pragma unroll
                for (int ng = 0; ng < 2; ng++) {
                    int r = rin[ng];
                    unsigned sw = (unsigned)(r * 128 + ((chb ^ (r & 7)) << 4));
                    unsigned r0, r1, r2, r3;
                    ldsm4(r0, r1, r2, r3, sb + XH + sw);
                    bh[2 * ng][0] = r0; bh[2 * ng][1] = r1;
                    bh[2 * ng + 1][0] = r2; bh[2 * ng + 1][1] = r3;
                    ldsm4(r0, r1, r2, r3, sb + XL + sw);
                    bl[2 * ng][0] = r0; bl[2 * ng][1] = r1;
                    bl[2 * ng + 1][0] = r2; bl[2 * ng + 1][1] = r3;
                }
                int cha = k16 * 2 + (mat >> 1);
#pragma unroll
                for (int mi = 0; mi < 2; mi++) {
                    int row = tap * 32 + mi * 16 + ri + ((mat & 1) << 3);
                    unsigned ad = sb + AH + row * 128 + ((cha ^ (row & 7)) << 4);
                    ldsm4(af[mi][0], af[mi][1], af[mi][2], af[mi][3], ad);
                }
#pragma unroll
                for (int mi = 0; mi < 2; mi++)
#pragma unroll
                    for (int ni = 0; ni < 4; ni++) {
                        mma16816(acc[mi][ni], af[mi], bh[ni]);
                        mma16816(acc[mi][ni], af[mi], bl[ni]);
                    }
#pragma unroll
                for (int mi = 0; mi < 2; mi++) {
                    int row = tap * 32 + mi * 16 + ri + ((mat & 1) << 3);
                    unsigned ad = sb + AL + row * 128 + ((cha ^ (row & 7)) << 4);
                    ldsm4(af[mi][0], af[mi][1], af[mi][2], af[mi][3], ad);
                }
#pragma unroll
                for (int mi = 0; mi < 2; mi++)
#pragma unroll
                    for (int ni = 0; ni < 4; ni++)
                        mma16816(acc[mi][ni], af[mi], bh[ni]);
            }
        }

#pragma unroll
        for (int mi = 0; mi < 2; mi++) {
            int oc0 = mi * 16 + (lane >> 2);
            float bias0 = ba[oc0], bias1 = ba[oc0 + 8];
#pragma unroll
            for (int ni = 0; ni < 4; ni++) {
                int t0 = n_base + ni * 8 + (lane & 3) * 2;
#pragma unroll
                for (int q = 0; q < 4; q++) {
                    int oc = (q < 2) ? oc0 : oc0 + 8;
                    float v = fmaxf(acc[mi][ni][q] + ((q < 2) ? bias0 : bias1), 0.f);
                    int t = t0 + (q & 1);
                    long base = (long)b * 16384 + t * 64 + oc;
                    __nv_bfloat16 h = __float2bfloat16(v);
                    g_c2h[base] = h;
                    g_c2l[base] = __float2bfloat16(v - __bfloat162float(h));
                }
            }
        }
    }
}

// ======================= Layer 2 kNN branch (mma M-table, fp32 distances) =======
__global__ __launch_bounds__(288, 2) void k_l2_knn(const int* __restrict__ idx,
                                                   const float* __restrict__ bb) {
    extern __shared__ __align__(16) char smem[];
    unsigned sb = smem_u32(smem);
    float* ss = (float*)smem;
    float* sn = (float*)(smem + 16896);
    const unsigned SH = 17152, SL = 17152 + 8192;
    float* Mt = (float*)(smem + 17152);
    int b = blockIdx.x, tid = threadIdx.x, lane = tid & 31, wid = tid >> 5;

    for (int i = tid; i < 4096; i += 288) {
        int n = i & 63, c = i >> 6;
        ss[n * 66 + c] = g_out1[(b * 64 + c) * 256 + idx[n]];
    }
    __syncthreads();
    for (int i = tid; i < 2048; i += 288) {
        int n = i >> 5, cp = (i & 31) * 2;
        float f0 = ss[n * 66 + cp], f1 = ss[n * 66 + cp + 1];
        int ch = cp >> 3;
        unsigned off = (unsigned)(n * 128 + ((ch ^ (n & 7)) << 4) + (cp & 7) * 2);
        __nv_bfloat16 h0 = __float2bfloat16(f0), h1 = __float2bfloat16(f1);
        *(unsigned*)(smem + SH + off) = pkbf(f0, f1);
        *(unsigned*)(smem + SL + off) =
            pkbf(f0 - __bfloat162float(h0), f1 - __bfloat162float(h1));
    }
    if (tid < 64) {
        float s = 0.f;
#pragma unroll 16
        for (int c = 0; c < 64; c++) { float v = ss[tid * 66 + c]; s += v * v; }
        sn[tid] = s;
    }
    __syncthreads();

    int ri = lane & 7, mat = lane >> 3;
    float acc[2][8][4];
#pragma unroll
    for (int i = 0; i < 2; i++)
#pragma unroll
        for (int j = 0; j < 8; j++)
#pragma unroll
            for (int q = 0; q < 4; q++) acc[i][j][q] = 0.f;

    {
        int w = wid;
        int arow = (lane >> 2), acol = (lane & 3) * 2;
#pragma unroll
        for (int k16 = 0; k16 < 4; k16++) {
#pragma unroll
            for (int half = 0; half < 2; half++) {
                unsigned bh[4][2], bl[4][2];
                int chb = k16 * 2 + (mat & 1);
#pragma unroll
                for (int ng = 0; ng < 2; ng++) {
                    int row = half * 32 + ng * 16 + ri + ((mat >> 1) << 3);
                    unsigned sw = (unsigned)(row * 128 + ((chb ^ (row & 7)) << 4));
                    unsigned r0, r1, r2, r3;
                    ldsm4(r0, r1, r2, r3, sb + SH + sw);
                    bh[2 * ng][0] = r0; bh[2 * ng][1] = r1;
                    bh[2 * ng + 1][0] = r2; bh[2 * ng + 1][1] = r3;
                    ldsm4(r0, r1, r2, r3, sb + SL + sw);
                    bl[2 * ng][0] = r0; bl[2 * ng][1] = r1;
                    bl[2 * ng + 1][0] = r2; bl[2 * ng + 1][1] = r3;
                }
#pragma unroll
                for (int mi = 0; mi < 2; mi++) {
                    long wbase = (long)(w * 32 + mi * 16 + arow) * 64 + k16 * 16 + acol;
                    unsigned ah[4];
                    ah[0] = *(const unsigned*)(g_w2bh + wbase);
                    ah[1] = *(const unsigned*)(g_w2bh + wbase + 8 * 64);
                    ah[2] = *(const unsigned*)(g_w2bh + wbase + 8);
                    ah[3] = *(const unsigned*)(g_w2bh + wbase + 8 * 64 + 8);
#pragma unroll
                    for (int nj = 0; nj < 4; nj++) {
                        mma16816(acc[mi][half * 4 + nj], ah, bh[nj]);
                        mma16816(acc[mi][half * 4 + nj], ah, bl[nj]);
                    }
                    ah[0] = *(const unsigned*)(g_w2bl + wbase);
                    ah[1] = *(const unsigned*)(g_w2bl + wbase + 8 * 64);
                    ah[2] = *(const unsigned*)(g_w2bl + wbase + 8);
                    ah[3] = *(const unsigned*)(g_w2bl + wbase + 8 * 64 + 8);
#pragma unroll
                    for (int nj = 0; nj < 4; nj++)
                        mma16816(acc[mi][half * 4 + nj], ah, bh[nj]);
                }
            }
        }
    }
    __syncthreads();

    {
        int w = wid;
#pragma unroll
        for (int mi = 0; mi < 2; mi++) {
            int oc0 = mi * 16 + (lane >> 2);
#pragma unroll
            for (int nj = 0; nj < 8; nj++) {
                int n0 = nj * 8 + (lane & 3) * 2;
#pragma unroll
                for (int q = 0; q < 4; q++) {
                    int oc = (q < 2) ? oc0 : oc0 + 8;
                    int n = n0 + (q & 1);
                    Mt[(w * 64 + n) * 36 + oc] = acc[mi][nj][q];
                }
            }
        }
    }
    __syncthreads();

    if (tid < 256) {
        int t = tid;
        ull xr2[32]; float xn = 0.f;
#pragma unroll
        for (int c2 = 0; c2 < 32; c2++) {
            float f0 = g_out1[(b * 64 + 2 * c2) * 256 + t];
            float f1 = g_out1[(b * 64 + 2 * c2 + 1) * 256 + t];
            xn += f0 * f0 + f1 * f1;
            xr2[c2] = pack2(f0, f1);
        }

        float bd[9]; int bi[9];
#pragma unroll
        for (int k = 0; k < 9; k++) { bd[k] = 3.0e38f; bi[k] = 0; }
        for (int n = 0; n < 64; n++) {
            const ull* sp = (const ull*)&ss[n * 66];
            ull d2 = 0ull;
#pragma unroll
            for (int j = 0; j < 32; j++) fma2(d2, xr2[j], sp[j]);
            float2 dv = unpk(d2);
            float d = xn + sn[n] - 2.f * (dv.x + dv.y);
            if (d < bd[8]) {
                bool placed = false;
#pragma unroll
                for (int j = 8; j > 0; --j) {
                    if (!placed) {
                        if (d < bd[j - 1]) { bd[j] = bd[j - 1]; bi[j] = bi[j - 1]; }
                        else { bd[j] = d; bi[j] = n; placed = true; }
                    }
                }
                if (!placed) { bd[0] = d; bi[0] = n; }
            }
        }

#pragma unroll
        for (int half = 0; half < 2; half++) {
            float acm[16];
#pragma unroll
            for (int o = 0; o < 16; o++) acm[o] = bb[half * 16 + o];
#pragma unroll
            for (int k = 0; k < 9; k++) {
                const float4* m4 = (const float4*)&Mt[(k * 64 + bi[k]) * 36 + half * 16];
                float4 v0 = m4[0], v1 = m4[1], v2 = m4[2], v3 = m4[3];
                acm[0] += v0.x; acm[1] += v0.y; acm[2] += v0.z; acm[3] += v0.w;
                acm[4] += v1.x; acm[5] += v1.y; acm[6] += v1.z; acm[7] += v1.w;
                acm[8] += v2.x; acm[9] += v2.y; acm[10] += v2.z; acm[11] += v2.w;
                acm[12] += v3.x; acm[13] += v3.y; acm[14] += v3.z; acm[15] += v3.w;
            }
#pragma unroll
            for (int j = 0; j < 8; j++)
                c2_store((long)b * 16384 + t * 64 + 32 + half * 16 + 2 * j,
                         fmaxf(acm[2 * j], 0.f), fmaxf(acm[2 * j + 1], 0.f));
        }
    }
}

// ===== Layer 2 pw as bf16 split mma, persistent over 2 images ===================
// smem: cat2 Bh 32K | Bl 32K | W Ah 16K | Al 16K = 96 KB; W staged once.
__global__ __launch_bounds__(256) void k_l2_pw(const float* __restrict__ bp) {
    extern __shared__ __align__(16) char smem[];
    unsigned sb = smem_u32(smem);
    int tid = threadIdx.x, lane = tid & 31, warp = tid >> 5;

    // weights: staged ONCE for both images
#pragma unroll
    for (int j = 0; j < 4; j++) {
        int q = tid + j * 256;
        int row = q >> 3, ch = q & 7;
        unsigned dst = sb + 65536 + row * 128 + ((ch ^ (row & 7)) << 4);
        cpa16(dst, g_wph + row * 64 + ch * 8);
        cpa16(dst + 16384, g_wpl + row * 64 + ch * 8);
    }
    cpa_commit();

    int m_base = (warp & 1) * 64;
    int n_base = (warp >> 1) * 64;
    int ri = lane & 7, mat = lane >> 3;

    for (int img = 0; img < 2; img++) {
        int b = blockIdx.x * 2 + img;
        __syncthreads();   // img>0: previous B reads done before overwrite
#pragma unroll
        for (int j = 0; j < 8; j++) {
            int q = tid + j * 256;
            int row = q >> 3, ch = q & 7;
            unsigned dst = sb + row * 128 + ((ch ^ (row & 7)) << 4);
            cpa16(dst, g_c2h + (long)b * 16384 + row * 64 + ch * 8);
            cpa16(dst + 32768, g_c2l + (long)b * 16384 + row * 64 + ch * 8);
        }
        cpa_commit();
        cpa_wait0();
        __syncthreads();

        float acc[4][8][4];
#pragma unroll
        for (int i = 0; i < 4; i++)
#pragma unroll
            for (int j = 0; j < 8; j++)
#pragma unroll
                for (int q = 0; q < 4; q++) acc[i][j][q] = 0.f;

#pragma unroll
        for (int kk = 0; kk < 4; kk++) {
            unsigned af[4][4], bh[8][2], bl[8][2];
#pragma unroll
            for (int ng = 0; ng < 4; ng++) {
                int row = n_base + ng * 16 + ri + ((mat >> 1) << 3);
                int ch = kk * 2 + (mat & 1);
                unsigned bd_ = sb + row * 128 + ((ch ^ (row & 7)) << 4);
                unsigned r0, r1, r2, r3;
                ldsm4(r0, r1, r2, r3, bd_);
                bh[2 * ng][0] = r0; bh[2 * ng][1] = r1;
                bh[2 * ng + 1][0] = r2; bh[2 * ng + 1][1] = r3;
                ldsm4(r0, r1, r2, r3, bd_ + 32768);
                bl[2 * ng][0] = r0; bl[2 * ng][1] = r1;
                bl[2 * ng + 1][0] = r2; bl[2 * ng + 1][1] = r3;
            }
#pragma unroll
            for (int mi = 0; mi < 4; mi++) {
                int row = m_base + mi * 16 + ri + ((mat & 1) << 3);
                int ch = kk * 2 + (mat >> 1);
                unsigned ad = sb + 65536 + row * 128 + ((ch ^ (row & 7)) << 4);
                ldsm4(af[mi][0], af[mi][1], af[mi][2], af[mi][3], ad);
            }
#pragma unroll
            for (int mi = 0; mi < 4; mi++)
#pragma unroll
                for (int ni = 0; ni < 8; ni++) {
                    mma16816(acc[mi][ni], af[mi], bh[ni]);
                    mma16816(acc[mi][ni], af[mi], bl[ni]);
                }
#pragma unroll
            for (int mi = 0; mi < 4; mi++) {
                int row = m_base + mi * 16 + ri + ((mat & 1) << 3);
                int ch = kk * 2 + (mat >> 1);
                unsigned ad = sb + 81920 + row * 128 + ((ch ^ (row & 7)) << 4);
                ldsm4(af[mi][0], af[mi][1], af[mi][2], af[mi][3], ad);
            }
#pragma unroll
            for (int mi = 0; mi < 4; mi++)
#pragma unroll
                for (int ni = 0; ni < 8; ni++)
                    mma16816(acc[mi][ni], af[mi], bh[ni]);
        }

#pragma unroll
        for (int mi = 0; mi < 4; mi++) {
            int oc0 = m_base + mi * 16 + (lane >> 2);
            float bias0 = bp[oc0], bias1 = bp[oc0 + 8];
#pragma unroll
            for (int ni = 0; ni < 8; ni++) {
                int t0 = n_base + ni * 8 + (lane & 3) * 2;
#pragma unroll
                for (int q = 0; q < 4; q++) {
                    int oc = (q < 2) ? oc0 : oc0 + 8;
                    float v = acc[mi][ni][q] + ((q < 2) ? bias0 : bias1);
                    int t = t0 + (q & 1);
                    int cp = oc >> 2, ii = (oc >> 1) & 1, jj = oc & 1;
                    int h = t >> 4, w = t & 15;
                    long pos = (long)b * 32768 + cp * 1024 + (2 * h + ii) * 32 + 2 * w + jj;
                    __nv_bfloat16 hi = __float2bfloat16(v);
                    g_ahi[pos] = hi;
                    g_alo[pos] = __float2bfloat16(v - __bfloat162float(hi));
                }
            }
        }
    }
}

// ======================= fc1: bf16 split GEMM, 3-stage pipeline =================
__global__ __launch_bounds__(512) void k_fc1t(const float* __restrict__ W) {
    extern __shared__ __align__(16) char smem[];
    unsigned sbase = smem_u32(smem);
    int tid = threadIdx.x, lane = tid & 31, warp = tid >> 5;
    int n0 = blockIdx.x * 128, sk = blockIdx.z;
    long kbase = (long)sk * 2048;

    int m_base = (warp & 3) * 64;
    int n_base = (warp >> 2) * 32;

    int aq[2], ac[2];
#pragma unroll
    for (int j = 0; j < 2; j++) { int q = tid + j * 512; aq[j] = q >> 2; ac[j] = q & 3; }
    int wr = tid >> 2, wc = tid & 3;

    float acc[4][4][4];
#pragma unroll
    for (int i = 0; i < 4; i++)
#pragma unroll
        for (int j = 0; j < 4; j++)
#pragma unroll
            for (int q = 0; q < 4; q++) acc[i][j][q] = 0.f;

    const float* wgp = W + (long)(n0 + wr) * 32768 + kbase + wc * 8;

    float4 wa0 = *(const float4*)(wgp), wb0 = *(const float4*)(wgp + 4);
    float4 wa1 = *(const float4*)(wgp + 32), wb1 = *(const float4*)(wgp + 36);
#pragma unroll
    for (int j = 0; j < 2; j++) {
        int r = aq[j], c = ac[j];
        unsigned sw = (unsigned)(r * 64 + ((c ^ ((r >> 1) & 3)) << 4));
        cpa16(sbase + sw, g_ahi + (long)r * 32768 + kbase + c * 8);
        cpa16(sbase + 16384 + sw, g_alo + (long)r * 32768 + kbase + c * 8);
    }
    cpa_commit();
#pragma unroll
    for (int j = 0; j < 2; j++) {
        int r = aq[j], c = ac[j];
        unsigned sw = (unsigned)(r * 64 + ((c ^ ((r >> 1) & 3)) << 4));
        cpa16(sbase + 49152 + sw, g_ahi + (long)r * 32768 + kbase + 32 + c * 8);
        cpa16(sbase + 49152 + 16384 + sw, g_alo + (long)r * 32768 + kbase + 32 + c * 8);
    }
    cpa_commit();
    wsplit_store(sbase + 32768, wr, wc, wa0, wb0);
    wsplit_store(sbase + 49152 + 32768, wr, wc, wa1, wb1);

    int ri = lane & 7, mat = lane >> 3;

    for (int it = 0; it < 64; it++) {
        unsigned stb = sbase + (unsigned)(it % 3) * 49152u;
        cpa_wait1();
        __syncthreads();

        float4 wna, wnb;
        unsigned nb = sbase + (unsigned)((it + 2) % 3) * 49152u;
        if (it < 62) {
            long ko = kbase + (it + 2) * 32;
            wna = *(const float4*)(wgp + (it + 2) * 32);
            wnb = *(const float4*)(wgp + (it + 2) * 32 + 4);
#pragma unroll
            for (int j = 0; j < 2; j++) {
                int r = aq[j], c = ac[j];
                unsigned sw = (unsigned)(r * 64 + ((c ^ ((r >> 1) & 3)) << 4));
                cpa16(nb + sw, g_ahi + (long)r * 32768 + ko + c * 8);
                cpa16(nb + 16384 + sw, g_alo + (long)r * 32768 + ko + c * 8);
            }
        }
        cpa_commit();

#pragma unroll
        for (int k16 = 0; k16 < 2; k16++) {
            unsigned af[4][4], bh[4][2], bl[4][2];
#pragma unroll
            for (int ng = 0; ng < 2; ng++) {
                int row = n_base + ng * 16 + ri + ((mat >> 1) << 3);
                int c = k16 * 2 + (mat & 1);
                unsigned bd_ = stb + 32768 + row * 64 + ((c ^ ((row >> 1) & 3)) << 4);
                unsigned r0, r1, r2, r3;
                ldsm4(r0, r1, r2, r3, bd_);
                bh[2 * ng][0] = r0; bh[2 * ng][1] = r1;
                bh[2 * ng + 1][0] = r2; bh[2 * ng + 1][1] = r3;
                ldsm4(r0, r1, r2, r3, bd_ + 8192);
                bl[2 * ng][0] = r0; bl[2 * ng][1] = r1;
                bl[2 * ng + 1][0] = r2; bl[2 * ng + 1][1] = r3;
            }
#pragma unroll
            for (int mi = 0; mi < 4; mi++) {
                int row = m_base + mi * 16 + ri + ((mat & 1) << 3);
                int c = k16 * 2 + (mat >> 1);
                unsigned ad = stb + row * 64 + ((c ^ ((row >> 1) & 3)) << 4);
                ldsm4(af[mi][0], af[mi][1], af[mi][2], af[mi][3], ad);
            }
#pragma unroll
            for (int mi = 0; mi < 4; mi++)
#pragma unroll
                for (int ni = 0; ni < 4; ni++) {
                    mma16816(acc[mi][ni], af[mi], bh[ni]);
                    mma16816(acc[mi][ni], af[mi], bl[ni]);
                }
#pragma unroll
            for (int mi = 0; mi < 4; mi++) {
                int row = m_base + mi * 16 + ri + ((mat & 1) << 3);
                int c = k16 * 2 + (mat >> 1);
                unsigned ad = stb + 16384 + row * 64 + ((c ^ ((row >> 1) & 3)) << 4);
                ldsm4(af[mi][0], af[mi][1], af[mi][2], af[mi][3], ad);
            }
#pragma unroll
            for (int mi = 0; mi < 4; mi++)
#pragma unroll
                for (int ni = 0; ni < 4; ni++)
                    mma16816(acc[mi][ni], af[mi], bh[ni]);
        }

        if (it < 62)
            wsplit_store(nb + 32768, wr, wc, wna, wnb);
    }

    float* slab = g_fc1p + (long)sk * BATCH * 1024;
#pragma unroll
    for (int mi = 0; mi < 4; mi++)
#pragma unroll
        for (int ni = 0; ni < 4; ni++) {
            int m = m_base + mi * 16 + (lane >> 2);
            int n = n0 + n_base + ni * 8 + (lane & 3) * 2;
            *(float2*)&slab[(long)m * 1024 + n] =
                make_float2(acc[mi][ni][0], acc[mi][ni][1]);
            *(float2*)&slab[(long)(m + 8) * 1024 + n] =
                make_float2(acc[mi][ni][2], acc[mi][ni][3]);
        }
}

// ======================= fc2 (fused slab-reduce + relu + fc2) ===================
__global__ __launch_bounds__(256) void k_fc2(const float* __restrict__ fc1b,
                                             const float* __restrict__ w2,
                                             const float* __restrict__ b2,
                                             float* __restrict__ out) {
    __shared__ __align__(16) float hs[1024];
    __shared__ float red[10 * 256];
    int b = blockIdx.x, tid = threadIdx.x;
    for (int j = tid; j < 1024; j += 256) {
        float s = 0.f;
#pragma unroll
        for (int q = 0; q < 16; q++) s += g_fc1p[(long)q * BATCH * 1024 + b * 1024 + j];
        hs[j] = fmaxf(s + fc1b[j], 0.f);
    }
    __syncthreads();
    float p[10];
#pragma unroll
    for (int n = 0; n < 10; n++) p[n] = 0.f;
    for (int j = tid; j < 1024; j += 256) {
        float hv = hs[j];
#pragma unroll
        for (int n = 0; n < 10; n++) p[n] += hv * w2[n * 1024 + j];
    }
#pragma unroll
    for (int n = 0; n < 10; n++) red[n * 256 + tid] = p[n];
    __syncthreads();
    for (int s = 128; s > 0; s >>= 1) {
        if (tid < s) {
#pragma unroll
            for (int n = 0; n < 10; n++) red[n * 256 + tid] += red[n * 256 + tid + s];
        }
        __syncthreads();
    }
    if (tid < 10) out[b * 10 + tid] = red[tid * 256] + b2[tid];
}

// =================================================================================
extern "C" void kernel_launch(void* const* d_in, const int* in_sizes, int n_in,
                              void* d_out, int out_size) {
    const float* x    = (const float*)d_in[0];
    const int*   idx1 = (const int*)d_in[1];
    const int*   idx2 = (const int*)d_in[2];
    const float* w1a  = (const float*)d_in[3];
    const float* b1a  = (const float*)d_in[4];
    const float* w1b  = (const float*)d_in[5];
    const float* b1b  = (const float*)d_in[6];
    const float* w1p  = (const float*)d_in[7];
    const float* b1p  = (const float*)d_in[8];
    const float* w2a  = (const float*)d_in[9];
    const float* b2a  = (const float*)d_in[10];
    const float* w2b  = (const float*)d_in[11];
    const float* b2b  = (const float*)d_in[12];
    const float* w2p  = (const float*)d_in[13];
    const float* b2p  = (const float*)d_in[14];
    const float* fc1w = (const float*)d_in[15];
    const float* fc1b = (const float*)d_in[16];
    const float* fc2w = (const float*)d_in[17];
    const float* fc2b = (const float*)d_in[18];
    float* out = (float*)d_out;

    const int smem_l2c  = 139776;
    const int smem_knn  = 100096;
    const int smem_pw   = 98304;
    const int smem_fc1t = 147456;
    cudaFuncSetAttribute(k_l2c,    cudaFuncAttributeMaxDynamicSharedMemorySize, smem_l2c);
    cudaFuncSetAttribute(k_l2_knn, cudaFuncAttributeMaxDynamicSharedMemorySize, smem_knn);
    cudaFuncSetAttribute(k_l2_pw,  cudaFuncAttributeMaxDynamicSharedMemorySize, smem_pw);
    cudaFuncSetAttribute(k_fc1t,   cudaFuncAttributeMaxDynamicSharedMemorySize, smem_fc1t);

    k_repack<<<72, 256>>>(w1a, w1b, w2a, w2b, w2p);
    k_l1<<<dim3(BATCH, 2), 128>>>(x, idx1, b1a, b1b, w1p, b1p);
    k_l2_knn<<<BATCH, 288, smem_knn>>>(idx2, b2b);
    k_l2c<<<BATCH / 2, 256, smem_l2c>>>(b2a);
    k_l2_pw<<<BATCH / 2, 256, smem_pw>>>(b2p);
    k_fc1t<<<dim3(8, 1, 16), 512, smem_fc1t>>>(fc1w);
    k_fc2<<<BATCH, 256>>>(fc1b, fc2w, fc2b, out);
}